// round 1
// baseline (speedup 1.0000x reference)
#include <cuda_runtime.h>
#include <math.h>

#define BB 4
#define NN 1024
#define HID 1024
#define NHEADS 16
#define DHEAD 64
#define MLPD 4096
#define ROWS (BB*NN)   // 4096

// ---------------- scratch (static device globals; no allocation) ----------------
__device__ float g_s_cond[HID];
__device__ float g_s_qkv[HID];
__device__ float g_s_out[HID];
__device__ float g_s_mlp1[HID];
__device__ float g_s_mlp2[MLPD];
__device__ float g_ccs[BB*HID];
__device__ float g_cond[BB*2*HID];
__device__ float g_xc1[ROWS*HID];
__device__ float g_qkv[ROWS*3*HID];
__device__ float g_q[ROWS*HID];
__device__ float g_k[ROWS*HID];
__device__ float g_v[ROWS*HID];
__device__ float g_xattn[ROWS*HID];
__device__ float g_ao[ROWS*HID];
__device__ float g_xmid[ROWS*HID];
__device__ float g_xc2[ROWS*HID];
__device__ float g_h[ROWS*MLPD];
__device__ float g_h2[ROWS*MLPD];
__device__ float g_m[ROWS*HID];

#define MP_ADD_INV 1.3130643285972254f   // 1/sqrt(0.7^2+0.3^2)
#define INV_SILU 1.6778523489932886f     // 1/0.596

// ---------------- row scale for NormalizedDense ----------------
// s[i] = 1 / ((||w[i,:]|| * sqrt(cols) + 1e-4) * sqrt(rows))
__global__ void __launch_bounds__(256) rowscale_kernel(const float* __restrict__ w,
                                                       float* __restrict__ s,
                                                       int cols, float alpha, float sqin) {
    __shared__ float red[256];
    const int tid = threadIdx.x;
    const int row = blockIdx.x;
    const float* wr = w + (size_t)row * cols;
    float acc = 0.f;
    for (int j = tid; j < cols; j += 256) { float v = wr[j]; acc += v * v; }
    red[tid] = acc; __syncthreads();
    for (int st = 128; st > 0; st >>= 1) { if (tid < st) red[tid] += red[tid + st]; __syncthreads(); }
    if (tid == 0) s[row] = 1.f / ((sqrtf(red[0]) * alpha + 1e-4f) * sqin);
}

// ---------------- conditioning ----------------
__global__ void __launch_bounds__(256) cond_act_kernel(const float* __restrict__ c) {
    int idx = blockIdx.x * 256 + threadIdx.x;   // 4096 total
    float v = c[idx];
    float si = v / (1.f + expf(-v)) * INV_SILU;
    g_ccs[idx] = si * g_s_cond[idx & (HID - 1)];
}

// cond_out[b, j] = sum_i ccs[b,i] * w_cond[i, j]   (w_cond: [1024, 2048])
__global__ void __launch_bounds__(256) cond_gemm_kernel(const float* __restrict__ w) {
    __shared__ float cs[BB * HID];
    const int tid = threadIdx.x;
    for (int t = tid; t < BB * HID; t += 256) cs[t] = g_ccs[t];
    __syncthreads();
    int j = blockIdx.x * 256 + tid;     // 0..2047 over 8 blocks
    float a0 = 0.f, a1 = 0.f, a2 = 0.f, a3 = 0.f;
    for (int i = 0; i < HID; i++) {
        float wv = w[(size_t)i * (2 * HID) + j];
        a0 = fmaf(cs[i], wv, a0);
        a1 = fmaf(cs[HID + i], wv, a1);
        a2 = fmaf(cs[2 * HID + i], wv, a2);
        a3 = fmaf(cs[3 * HID + i], wv, a3);
    }
    g_cond[j] = a0;
    g_cond[2 * HID + j] = a1;
    g_cond[4 * HID + j] = a2;
    g_cond[6 * HID + j] = a3;
}

// ---------------- xcond: pixel_norm(x)*(1+gain)+shift, pre-scaled for next GEMM ----------------
__global__ void __launch_bounds__(256) xcond_kernel(const float* __restrict__ x,
                                                    const float* __restrict__ scale,
                                                    float* __restrict__ out) {
    __shared__ float buf[HID];
    __shared__ float red[256];
    const int tid = threadIdx.x;
    const int row = blockIdx.x;
    const int b = row >> 10;
    const float* xr = x + (size_t)row * HID;
    float acc = 0.f;
    for (int k = tid; k < HID; k += 256) { float v = xr[k]; buf[k] = v; acc += v * v; }
    red[tid] = acc; __syncthreads();
    for (int st = 128; st > 0; st >>= 1) { if (tid < st) red[tid] += red[tid + st]; __syncthreads(); }
    float rms = rsqrtf(red[0] * (1.f / HID) + 1e-4f);
    const float* gs = g_cond + (size_t)b * 2 * HID;
    for (int k = tid; k < HID; k += 256)
        out[(size_t)row * HID + k] = (buf[k] * rms * (1.f + gs[k]) + gs[HID + k]) * scale[k];
}

// ---------------- qkv normalize + head split ----------------
__global__ void __launch_bounds__(256) qkv_norm_kernel() {
    __shared__ float buf[3 * HID];
    __shared__ float red[768];
    __shared__ float hs[32];
    const int tid = threadIdx.x;
    const int row = blockIdx.x;           // b*N + n
    const float* qr = g_qkv + (size_t)row * 3 * HID;
    float aq = 0.f, ak = 0.f, av = 0.f;
    for (int k = tid; k < HID; k += 256) {
        float a = qr[k];           buf[k] = a;           aq += a * a;
        float bq = qr[HID + k];    buf[HID + k] = bq;    ak += bq * bq;
        float cv = qr[2*HID + k];  buf[2*HID + k] = cv;  av += cv * cv;
    }
    red[tid] = aq; red[256 + tid] = ak; red[512 + tid] = av; __syncthreads();
    for (int st = 128; st > 0; st >>= 1) {
        if (tid < st) {
            red[tid] += red[tid + st];
            red[256 + tid] += red[256 + tid + st];
            red[512 + tid] += red[512 + tid + st];
        }
        __syncthreads();
    }
    float rq = rsqrtf(red[0]   * (1.f / HID) + 1e-4f);
    float rk = rsqrtf(red[256] * (1.f / HID) + 1e-4f);
    float rv = rsqrtf(red[512] * (1.f / HID) + 1e-4f);
    __syncthreads();
    for (int k = tid; k < HID; k += 256) {
        buf[k] *= rq; buf[HID + k] *= rk; buf[2*HID + k] *= rv;
    }
    __syncthreads();
    // per-head l2 norms for q (hs[0..15]) and k (hs[16..31])
    if (tid < 32) {
        int hh = tid & 15;
        int base = ((tid >> 4) ? HID : 0) + hh * DHEAD;
        float s = 0.f;
        #pragma unroll
        for (int d = 0; d < DHEAD; d++) { float v = buf[base + d]; s += v * v; }
        hs[tid] = rsqrtf(s + 1e-6f);
    }
    __syncthreads();
    const int b = row >> 10, n = row & (NN - 1);
    for (int k = tid; k < HID; k += 256) {
        int hh = k >> 6, d = k & 63;
        size_t o = ((size_t)(b * NHEADS + hh) * NN + n) * DHEAD + d;
        g_q[o] = buf[k] * hs[hh];
        g_k[o] = buf[HID + k] * hs[16 + hh];
        g_v[o] = buf[2*HID + k];
    }
}

// ---------------- flash attention: 64 queries/CTA, stream 16 KV tiles ----------------
#define ATT_SMEM ((4096 + 64*66 + 4096) * 4)   // Qs + Kt(pad 66, reused for P) + Vs
__global__ void __launch_bounds__(256) attn_kernel() {
    extern __shared__ float sm[];
    float* Qs = sm;               // [64][64]
    float* Kt = sm + 4096;        // [64][66] transposed K; later P as [64q][66]
    float* Vs = Kt + 64 * 66;     // [64][64]
    const int tid = threadIdx.x;
    const int bh = blockIdx.y;
    const int q0 = blockIdx.x * 64;
    const int b = bh >> 4, h = bh & 15;
    const float* Qg = g_q + (size_t)bh * (NN * DHEAD) + (size_t)q0 * DHEAD;
    const float* Kg = g_k + (size_t)bh * (NN * DHEAD);
    const float* Vg = g_v + (size_t)bh * (NN * DHEAD);
    for (int t = tid; t < 4096; t += 256) Qs[t] = Qg[t] * 0.125f;  // fold 1/sqrt(DH)
    const int tr = (tid >> 4) << 2;
    const int tc = (tid & 15) << 2;
    float O[4][4];
    float rm[4], rl[4];
    #pragma unroll
    for (int i = 0; i < 4; i++) {
        rm[i] = -1e30f; rl[i] = 0.f;
        #pragma unroll
        for (int j = 0; j < 4; j++) O[i][j] = 0.f;
    }
    for (int kt = 0; kt < 16; kt++) {
        __syncthreads();
        for (int t = tid; t < 4096; t += 256) {
            int j = t >> 6, d = t & 63;
            Kt[d * 66 + j] = Kg[(size_t)kt * 4096 + t];
            Vs[t] = Vg[(size_t)kt * 4096 + t];
        }
        __syncthreads();
        float s[4][4];
        #pragma unroll
        for (int i = 0; i < 4; i++)
            #pragma unroll
            for (int j = 0; j < 4; j++) s[i][j] = 0.f;
        #pragma unroll 8
        for (int d = 0; d < 64; d++) {
            float qa[4], kb[4];
            #pragma unroll
            for (int i = 0; i < 4; i++) qa[i] = Qs[(tr + i) * 64 + d];
            #pragma unroll
            for (int j = 0; j < 4; j++) kb[j] = Kt[d * 66 + tc + j];
            #pragma unroll
            for (int i = 0; i < 4; i++)
                #pragma unroll
                for (int j = 0; j < 4; j++) s[i][j] = fmaf(qa[i], kb[j], s[i][j]);
        }
        __syncthreads();   // S reads of Kt done; P may overwrite
        #pragma unroll
        for (int i = 0; i < 4; i++) {
            float m = fmaxf(fmaxf(s[i][0], s[i][1]), fmaxf(s[i][2], s[i][3]));
            m = fmaxf(m, __shfl_xor_sync(0xffffffffu, m, 8));
            m = fmaxf(m, __shfl_xor_sync(0xffffffffu, m, 4));
            m = fmaxf(m, __shfl_xor_sync(0xffffffffu, m, 2));
            m = fmaxf(m, __shfl_xor_sync(0xffffffffu, m, 1));
            float nm = fmaxf(rm[i], m);
            float l = 0.f;
            #pragma unroll
            for (int j = 0; j < 4; j++) { s[i][j] = __expf(s[i][j] - nm); l += s[i][j]; }
            l += __shfl_xor_sync(0xffffffffu, l, 8);
            l += __shfl_xor_sync(0xffffffffu, l, 4);
            l += __shfl_xor_sync(0xffffffffu, l, 2);
            l += __shfl_xor_sync(0xffffffffu, l, 1);
            float al = __expf(rm[i] - nm);
            rl[i] = rl[i] * al + l;
            rm[i] = nm;
            #pragma unroll
            for (int j = 0; j < 4; j++) O[i][j] *= al;
            #pragma unroll
            for (int j = 0; j < 4; j++) Kt[(tr + i) * 66 + tc + j] = s[i][j];
        }
        __syncthreads();   // P visible
        #pragma unroll 8
        for (int k2 = 0; k2 < 64; k2++) {
            float pa[4], vb[4];
            #pragma unroll
            for (int i = 0; i < 4; i++) pa[i] = Kt[(tr + i) * 66 + k2];
            #pragma unroll
            for (int j = 0; j < 4; j++) vb[j] = Vs[k2 * 64 + tc + j];
            #pragma unroll
            for (int i = 0; i < 4; i++)
                #pragma unroll
                for (int j = 0; j < 4; j++) O[i][j] = fmaf(pa[i], vb[j], O[i][j]);
        }
    }
    #pragma unroll
    for (int i = 0; i < 4; i++) {
        float inv = 1.f / rl[i];
        int n = q0 + tr + i;
        #pragma unroll
        for (int j = 0; j < 4; j++) {
            int hd = h * DHEAD + tc + j;
            g_xattn[((size_t)b * NN + n) * HID + hd] = O[i][j] * inv * g_s_out[hd];
        }
    }
}

// ---------------- generic fp32 SGEMM: C[M,N] = A[M,K] @ B[K,N], all dims %128==0 ----------------
__global__ void __launch_bounds__(256) sgemm128(const float* __restrict__ A,
                                                const float* __restrict__ Bm,
                                                float* __restrict__ C,
                                                int M, int Nn, int K) {
    __shared__ float As[8][128];
    __shared__ float Bs[8][128];
    const int tid = threadIdx.x;
    const int crow = blockIdx.y * 128;
    const int ccol = blockIdx.x * 128;
    const int arow = tid >> 1;
    const int acol = (tid & 1) << 2;
    const int brow = tid >> 5;
    const int bcol = (tid & 31) << 2;
    const float* Ap = A + (size_t)(crow + arow) * K + acol;
    const float* Bp = Bm + (size_t)brow * Nn + ccol + bcol;
    const int tr = (tid >> 4) << 3;
    const int tc = (tid & 15) << 3;
    float acc[8][8];
    #pragma unroll
    for (int i = 0; i < 8; i++)
        #pragma unroll
        for (int j = 0; j < 8; j++) acc[i][j] = 0.f;
    for (int k0 = 0; k0 < K; k0 += 8) {
        float4 avv = *(const float4*)Ap;
        float4 bvv = *(const float4*)Bp;
        As[acol + 0][arow] = avv.x;
        As[acol + 1][arow] = avv.y;
        As[acol + 2][arow] = avv.z;
        As[acol + 3][arow] = avv.w;
        *(float4*)&Bs[brow][bcol] = bvv;
        __syncthreads();
        #pragma unroll
        for (int kk = 0; kk < 8; kk++) {
            float ra[8], rb[8];
            *(float4*)&ra[0] = *(const float4*)&As[kk][tr];
            *(float4*)&ra[4] = *(const float4*)&As[kk][tr + 4];
            *(float4*)&rb[0] = *(const float4*)&Bs[kk][tc];
            *(float4*)&rb[4] = *(const float4*)&Bs[kk][tc + 4];
            #pragma unroll
            for (int i = 0; i < 8; i++)
                #pragma unroll
                for (int j = 0; j < 8; j++) acc[i][j] = fmaf(ra[i], rb[j], acc[i][j]);
        }
        __syncthreads();
        Ap += 8;
        Bp += (size_t)8 * Nn;
    }
    #pragma unroll
    for (int i = 0; i < 8; i++) {
        float* Cp = C + (size_t)(crow + tr + i) * Nn + ccol + tc;
        *(float4*)Cp       = make_float4(acc[i][0], acc[i][1], acc[i][2], acc[i][3]);
        *(float4*)(Cp + 4) = make_float4(acc[i][4], acc[i][5], acc[i][6], acc[i][7]);
    }
}

// ---------------- post-attention: pn(ao)*e^g, mp_add, then xcond2 for MLP ----------------
__global__ void __launch_bounds__(256) post_attn_kernel(const float* __restrict__ x,
                                                        const float* __restrict__ agp) {
    __shared__ float buf[HID];
    __shared__ float red[256];
    const int tid = threadIdx.x;
    const int row = blockIdx.x;
    const int b = row >> 10;
    const float* ar = g_ao + (size_t)row * HID;
    float acc = 0.f;
    for (int k = tid; k < HID; k += 256) { float v = ar[k]; buf[k] = v; acc += v * v; }
    red[tid] = acc; __syncthreads();
    for (int st = 128; st > 0; st >>= 1) { if (tid < st) red[tid] += red[tid + st]; __syncthreads(); }
    float rms = rsqrtf(red[0] * (1.f / HID) + 1e-4f);
    float eg = expf(agp[0]);
    const float* xr = x + (size_t)row * HID;
    float acc2 = 0.f;
    for (int k = tid; k < HID; k += 256) {
        float xa = buf[k] * rms * eg;
        float xm = (0.7f * xr[k] + 0.3f * xa) * MP_ADD_INV;
        g_xmid[(size_t)row * HID + k] = xm;
        buf[k] = xm;
        acc2 += xm * xm;
    }
    __syncthreads();
    red[tid] = acc2; __syncthreads();
    for (int st = 128; st > 0; st >>= 1) { if (tid < st) red[tid] += red[tid + st]; __syncthreads(); }
    float rms2 = rsqrtf(red[0] * (1.f / HID) + 1e-4f);
    const float* gs = g_cond + (size_t)b * 2 * HID;
    for (int k = tid; k < HID; k += 256)
        g_xc2[(size_t)row * HID + k] = (buf[k] * rms2 * (1.f + gs[k]) + gs[HID + k]) * g_s_mlp1[k];
}

// ---------------- MLP hidden: pixel_norm over 4096, mp_silu, scale for mlp2 ----------------
__global__ void __launch_bounds__(256) mlp_act_kernel() {
    __shared__ float buf[MLPD];
    __shared__ float red[256];
    const int tid = threadIdx.x;
    const int row = blockIdx.x;
    const float* hr = g_h + (size_t)row * MLPD;
    float acc = 0.f;
    for (int k = tid; k < MLPD; k += 256) { float v = hr[k]; buf[k] = v; acc += v * v; }
    red[tid] = acc; __syncthreads();
    for (int st = 128; st > 0; st >>= 1) { if (tid < st) red[tid] += red[tid + st]; __syncthreads(); }
    float rms = rsqrtf(red[0] * (1.f / MLPD) + 1e-4f);
    for (int k = tid; k < MLPD; k += 256) {
        float u = buf[k] * rms;
        float si = u / (1.f + expf(-u)) * INV_SILU;
        g_h2[(size_t)row * MLPD + k] = si * g_s_mlp2[k];
    }
}

// ---------------- final: pn(m)*e^g, mp_add with xmid ----------------
__global__ void __launch_bounds__(256) final_kernel(const float* __restrict__ mgp,
                                                    float* __restrict__ out) {
    __shared__ float buf[HID];
    __shared__ float red[256];
    const int tid = threadIdx.x;
    const int row = blockIdx.x;
    const float* mr = g_m + (size_t)row * HID;
    float acc = 0.f;
    for (int k = tid; k < HID; k += 256) { float v = mr[k]; buf[k] = v; acc += v * v; }
    red[tid] = acc; __syncthreads();
    for (int st = 128; st > 0; st >>= 1) { if (tid < st) red[tid] += red[tid + st]; __syncthreads(); }
    float rms = rsqrtf(red[0] * (1.f / HID) + 1e-4f);
    float eg = expf(mgp[0]);
    for (int k = tid; k < HID; k += 256) {
        float xm = buf[k] * rms * eg;
        out[(size_t)row * HID + k] = (0.7f * g_xmid[(size_t)row * HID + k] + 0.3f * xm) * MP_ADD_INV;
    }
}

// ---------------- launch ----------------
extern "C" void kernel_launch(void* const* d_in, const int* in_sizes, int n_in,
                              void* d_out, int out_size) {
    (void)in_sizes; (void)n_in; (void)out_size;
    const float* x         = (const float*)d_in[0];
    const float* c         = (const float*)d_in[1];
    const float* w_cond    = (const float*)d_in[2];
    const float* w_qkv     = (const float*)d_in[3];
    const float* w_out     = (const float*)d_in[4];
    const float* w_mlp1    = (const float*)d_in[5];
    const float* w_mlp2    = (const float*)d_in[6];
    const float* attn_gain = (const float*)d_in[7];
    const float* mlp_gain  = (const float*)d_in[8];
    float* out = (float*)d_out;

    void *p_scond, *p_sqkv, *p_sout, *p_smlp1, *p_smlp2;
    void *p_xc1, *p_qkv, *p_xattn, *p_ao, *p_xc2, *p_h, *p_h2, *p_m;
    cudaGetSymbolAddress(&p_scond, g_s_cond);
    cudaGetSymbolAddress(&p_sqkv,  g_s_qkv);
    cudaGetSymbolAddress(&p_sout,  g_s_out);
    cudaGetSymbolAddress(&p_smlp1, g_s_mlp1);
    cudaGetSymbolAddress(&p_smlp2, g_s_mlp2);
    cudaGetSymbolAddress(&p_xc1,   g_xc1);
    cudaGetSymbolAddress(&p_qkv,   g_qkv);
    cudaGetSymbolAddress(&p_xattn, g_xattn);
    cudaGetSymbolAddress(&p_ao,    g_ao);
    cudaGetSymbolAddress(&p_xc2,   g_xc2);
    cudaGetSymbolAddress(&p_h,     g_h);
    cudaGetSymbolAddress(&p_h2,    g_h2);
    cudaGetSymbolAddress(&p_m,     g_m);

    // weight row scales (fold NormalizedDense into activations)
    rowscale_kernel<<<1024, 256>>>(w_cond, (float*)p_scond, 2048, 45.25483399593904f, 32.f);
    rowscale_kernel<<<1024, 256>>>(w_qkv,  (float*)p_sqkv,  3072, 55.42562584220407f, 32.f);
    rowscale_kernel<<<1024, 256>>>(w_out,  (float*)p_sout,  1024, 32.f, 32.f);
    rowscale_kernel<<<1024, 256>>>(w_mlp1, (float*)p_smlp1, 4096, 64.f, 32.f);
    rowscale_kernel<<<4096, 256>>>(w_mlp2, (float*)p_smlp2, 1024, 32.f, 64.f);

    // conditioning -> gain/shift
    cond_act_kernel<<<16, 256>>>(c);
    cond_gemm_kernel<<<8, 256>>>(w_cond);

    // attention branch
    xcond_kernel<<<ROWS, 256>>>(x, (const float*)p_sqkv, (float*)p_xc1);
    sgemm128<<<dim3(24, 32), 256>>>((const float*)p_xc1, w_qkv, (float*)p_qkv, ROWS, 3 * HID, HID);
    qkv_norm_kernel<<<ROWS, 256>>>();
    cudaFuncSetAttribute(attn_kernel, cudaFuncAttributeMaxDynamicSharedMemorySize, ATT_SMEM);
    attn_kernel<<<dim3(16, 64), 256, ATT_SMEM>>>();
    sgemm128<<<dim3(8, 32), 256>>>((const float*)p_xattn, w_out, (float*)p_ao, ROWS, HID, HID);
    post_attn_kernel<<<ROWS, 256>>>(x, attn_gain);

    // MLP branch
    sgemm128<<<dim3(32, 32), 256>>>((const float*)p_xc2, w_mlp1, (float*)p_h, ROWS, MLPD, HID);
    mlp_act_kernel<<<ROWS, 256>>>();
    sgemm128<<<dim3(8, 32), 256>>>((const float*)p_h2, w_mlp2, (float*)p_m, ROWS, HID, MLPD);
    final_kernel<<<ROWS, 256>>>(mlp_gain, out);
}

// round 2
// speedup vs baseline: 2.3665x; 2.3665x over previous
#include <cuda_runtime.h>
#include <math.h>
#include <stdint.h>

#define BB 4
#define NN 1024
#define HID 1024
#define NHEADS 16
#define DHEAD 64
#define MLPD 4096
#define ROWS (BB*NN)   // 4096

// ---------------- scratch (static device globals; no allocation) ----------------
__device__ float g_s_cond[HID];
__device__ float g_ccs[BB*HID];
__device__ float g_cond[BB*2*HID];
__device__ float g_xc1[ROWS*HID];
__device__ float g_qkv[ROWS*3*HID];
__device__ float g_q[ROWS*HID];
__device__ float g_k[ROWS*HID];
__device__ float g_v[ROWS*HID];
__device__ float g_xattn[ROWS*HID];
__device__ float g_ao[ROWS*HID];
__device__ float g_xmid[ROWS*HID];
__device__ float g_xc2[ROWS*HID];
__device__ float g_h[ROWS*MLPD];
__device__ float g_h2[ROWS*MLPD];
__device__ float g_m[ROWS*HID];
// tf32 (rna-rounded) pre-scaled weights
__device__ float g_wq[HID*3*HID];
__device__ float g_wo[HID*HID];
__device__ float g_wm1[HID*MLPD];
__device__ float g_wm2[MLPD*HID];

#define MP_ADD_INV 1.3130643285972254f   // 1/sqrt(0.7^2+0.3^2)
#define INV_SILU 1.6778523489932886f     // 1/0.596

__device__ __forceinline__ float f2tf32(float x) {
    uint32_t u;
    asm("cvt.rna.tf32.f32 %0, %1;" : "=r"(u) : "f"(x));
    return __uint_as_float(u);
}

__device__ __forceinline__ void cp16(uint32_t dst, const void* src) {
    asm volatile("cp.async.cg.shared.global [%0], [%1], 16;" :: "r"(dst), "l"(src));
}
#define CP_COMMIT() asm volatile("cp.async.commit_group;")
#define CP_WAIT0()  asm volatile("cp.async.wait_group 0;")

__device__ __forceinline__ void mma_tf32(float* c, const uint32_t* a, const uint32_t* b) {
    asm volatile("mma.sync.aligned.m16n8k8.row.col.f32.tf32.tf32.f32 "
        "{%0,%1,%2,%3}, {%4,%5,%6,%7}, {%8,%9}, {%0,%1,%2,%3};"
        : "+f"(c[0]), "+f"(c[1]), "+f"(c[2]), "+f"(c[3])
        : "r"(a[0]), "r"(a[1]), "r"(a[2]), "r"(a[3]), "r"(b[0]), "r"(b[1]));
}

// ---------------- weight convert: row-normalize + scale + tf32 round ----------------
// wt[i,j] = tf32( w[i,j] / ((||w[i,:]||*alpha + 1e-4) * sqin) )
__global__ void __launch_bounds__(256) wconv_kernel(const float* __restrict__ w,
                                                    float* __restrict__ wt,
                                                    int cols, float alpha, float sqin) {
    __shared__ float red[256];
    const int tid = threadIdx.x;
    const int row = blockIdx.x;
    const float* wr = w + (size_t)row * cols;
    float acc = 0.f;
    for (int j = tid; j < cols; j += 256) { float v = wr[j]; acc += v * v; }
    red[tid] = acc; __syncthreads();
    for (int st = 128; st > 0; st >>= 1) { if (tid < st) red[tid] += red[tid + st]; __syncthreads(); }
    float s = 1.f / ((sqrtf(red[0]) * alpha + 1e-4f) * sqin);
    float* wo = wt + (size_t)row * cols;
    for (int j = tid; j < cols; j += 256) wo[j] = f2tf32(wr[j] * s);
}

// ---------------- rowscale (cond weight only, fp32 path) ----------------
__global__ void __launch_bounds__(256) rowscale_kernel(const float* __restrict__ w,
                                                       float* __restrict__ s,
                                                       int cols, float alpha, float sqin) {
    __shared__ float red[256];
    const int tid = threadIdx.x;
    const int row = blockIdx.x;
    const float* wr = w + (size_t)row * cols;
    float acc = 0.f;
    for (int j = tid; j < cols; j += 256) { float v = wr[j]; acc += v * v; }
    red[tid] = acc; __syncthreads();
    for (int st = 128; st > 0; st >>= 1) { if (tid < st) red[tid] += red[tid + st]; __syncthreads(); }
    if (tid == 0) s[row] = 1.f / ((sqrtf(red[0]) * alpha + 1e-4f) * sqin);
}

// ---------------- conditioning ----------------
__global__ void __launch_bounds__(256) cond_act_kernel(const float* __restrict__ c) {
    int idx = blockIdx.x * 256 + threadIdx.x;   // 4096 total
    float v = c[idx];
    float si = v / (1.f + expf(-v)) * INV_SILU;
    g_ccs[idx] = si * g_s_cond[idx & (HID - 1)];
}

__global__ void __launch_bounds__(256) cond_gemm_kernel(const float* __restrict__ w) {
    __shared__ float cs[BB * HID];
    const int tid = threadIdx.x;
    for (int t = tid; t < BB * HID; t += 256) cs[t] = g_ccs[t];
    __syncthreads();
    int j = blockIdx.x * 256 + tid;     // 0..2047 over 8 blocks
    float a0 = 0.f, a1 = 0.f, a2 = 0.f, a3 = 0.f;
    for (int i = 0; i < HID; i++) {
        float wv = w[(size_t)i * (2 * HID) + j];
        a0 = fmaf(cs[i], wv, a0);
        a1 = fmaf(cs[HID + i], wv, a1);
        a2 = fmaf(cs[2 * HID + i], wv, a2);
        a3 = fmaf(cs[3 * HID + i], wv, a3);
    }
    g_cond[j] = a0;
    g_cond[2 * HID + j] = a1;
    g_cond[4 * HID + j] = a2;
    g_cond[6 * HID + j] = a3;
}

// ---------------- xcond: tf32(pixel_norm(x)*(1+gain)+shift) ----------------
__global__ void __launch_bounds__(256) xcond_kernel(const float* __restrict__ x,
                                                    float* __restrict__ out) {
    __shared__ float buf[HID];
    __shared__ float red[256];
    const int tid = threadIdx.x;
    const int row = blockIdx.x;
    const int b = row >> 10;
    const float* xr = x + (size_t)row * HID;
    float acc = 0.f;
    for (int k = tid; k < HID; k += 256) { float v = xr[k]; buf[k] = v; acc += v * v; }
    red[tid] = acc; __syncthreads();
    for (int st = 128; st > 0; st >>= 1) { if (tid < st) red[tid] += red[tid + st]; __syncthreads(); }
    float rms = rsqrtf(red[0] * (1.f / HID) + 1e-4f);
    const float* gs = g_cond + (size_t)b * 2 * HID;
    for (int k = tid; k < HID; k += 256)
        out[(size_t)row * HID + k] = f2tf32(buf[k] * rms * (1.f + gs[k]) + gs[HID + k]);
}

// ---------------- qkv normalize + head split ----------------
__global__ void __launch_bounds__(256) qkv_norm_kernel() {
    __shared__ float buf[3 * HID];
    __shared__ float red[768];
    __shared__ float hs[32];
    const int tid = threadIdx.x;
    const int row = blockIdx.x;           // b*N + n
    const float* qr = g_qkv + (size_t)row * 3 * HID;
    float aq = 0.f, ak = 0.f, av = 0.f;
    for (int k = tid; k < HID; k += 256) {
        float a = qr[k];           buf[k] = a;           aq += a * a;
        float bq = qr[HID + k];    buf[HID + k] = bq;    ak += bq * bq;
        float cv = qr[2*HID + k];  buf[2*HID + k] = cv;  av += cv * cv;
    }
    red[tid] = aq; red[256 + tid] = ak; red[512 + tid] = av; __syncthreads();
    for (int st = 128; st > 0; st >>= 1) {
        if (tid < st) {
            red[tid] += red[tid + st];
            red[256 + tid] += red[256 + tid + st];
            red[512 + tid] += red[512 + tid + st];
        }
        __syncthreads();
    }
    float rq = rsqrtf(red[0]   * (1.f / HID) + 1e-4f);
    float rk = rsqrtf(red[256] * (1.f / HID) + 1e-4f);
    float rv = rsqrtf(red[512] * (1.f / HID) + 1e-4f);
    __syncthreads();
    for (int k = tid; k < HID; k += 256) {
        buf[k] *= rq; buf[HID + k] *= rk; buf[2*HID + k] *= rv;
    }
    __syncthreads();
    if (tid < 32) {
        int hh = tid & 15;
        int base = ((tid >> 4) ? HID : 0) + hh * DHEAD;
        float s = 0.f;
        #pragma unroll
        for (int d = 0; d < DHEAD; d++) { float v = buf[base + d]; s += v * v; }
        hs[tid] = rsqrtf(s + 1e-6f);
    }
    __syncthreads();
    const int b = row >> 10, n = row & (NN - 1);
    for (int k = tid; k < HID; k += 256) {
        int hh = k >> 6, d = k & 63;
        size_t o = ((size_t)(b * NHEADS + hh) * NN + n) * DHEAD + d;
        g_q[o] = buf[k] * hs[hh];
        g_k[o] = buf[HID + k] * hs[16 + hh];
        g_v[o] = buf[2*HID + k];
    }
}

// ---------------- flash attention (fp32 SIMT) ----------------
#define ATT_SMEM ((4096 + 64*66 + 4096) * 4)
__global__ void __launch_bounds__(256) attn_kernel() {
    extern __shared__ float sm[];
    float* Qs = sm;               // [64][64]
    float* Kt = sm + 4096;        // [64][66] transposed K; later P
    float* Vs = Kt + 64 * 66;     // [64][64]
    const int tid = threadIdx.x;
    const int bh = blockIdx.y;
    const int q0 = blockIdx.x * 64;
    const int b = bh >> 4, h = bh & 15;
    const float* Qg = g_q + (size_t)bh * (NN * DHEAD) + (size_t)q0 * DHEAD;
    const float* Kg = g_k + (size_t)bh * (NN * DHEAD);
    const float* Vg = g_v + (size_t)bh * (NN * DHEAD);
    for (int t = tid; t < 4096; t += 256) Qs[t] = Qg[t] * 0.125f;
    const int tr = (tid >> 4) << 2;
    const int tc = (tid & 15) << 2;
    float O[4][4];
    float rm[4], rl[4];
    #pragma unroll
    for (int i = 0; i < 4; i++) {
        rm[i] = -1e30f; rl[i] = 0.f;
        #pragma unroll
        for (int j = 0; j < 4; j++) O[i][j] = 0.f;
    }
    for (int kt = 0; kt < 16; kt++) {
        __syncthreads();
        for (int t = tid; t < 4096; t += 256) {
            int j = t >> 6, d = t & 63;
            Kt[d * 66 + j] = Kg[(size_t)kt * 4096 + t];
            Vs[t] = Vg[(size_t)kt * 4096 + t];
        }
        __syncthreads();
        float s[4][4];
        #pragma unroll
        for (int i = 0; i < 4; i++)
            #pragma unroll
            for (int j = 0; j < 4; j++) s[i][j] = 0.f;
        #pragma unroll 8
        for (int d = 0; d < 64; d++) {
            float qa[4], kb[4];
            #pragma unroll
            for (int i = 0; i < 4; i++) qa[i] = Qs[(tr + i) * 64 + d];
            #pragma unroll
            for (int j = 0; j < 4; j++) kb[j] = Kt[d * 66 + tc + j];
            #pragma unroll
            for (int i = 0; i < 4; i++)
                #pragma unroll
                for (int j = 0; j < 4; j++) s[i][j] = fmaf(qa[i], kb[j], s[i][j]);
        }
        __syncthreads();
        #pragma unroll
        for (int i = 0; i < 4; i++) {
            float m = fmaxf(fmaxf(s[i][0], s[i][1]), fmaxf(s[i][2], s[i][3]));
            m = fmaxf(m, __shfl_xor_sync(0xffffffffu, m, 8));
            m = fmaxf(m, __shfl_xor_sync(0xffffffffu, m, 4));
            m = fmaxf(m, __shfl_xor_sync(0xffffffffu, m, 2));
            m = fmaxf(m, __shfl_xor_sync(0xffffffffu, m, 1));
            float nm = fmaxf(rm[i], m);
            float l = 0.f;
            #pragma unroll
            for (int j = 0; j < 4; j++) { s[i][j] = __expf(s[i][j] - nm); l += s[i][j]; }
            l += __shfl_xor_sync(0xffffffffu, l, 8);
            l += __shfl_xor_sync(0xffffffffu, l, 4);
            l += __shfl_xor_sync(0xffffffffu, l, 2);
            l += __shfl_xor_sync(0xffffffffu, l, 1);
            float al = __expf(rm[i] - nm);
            rl[i] = rl[i] * al + l;
            rm[i] = nm;
            #pragma unroll
            for (int j = 0; j < 4; j++) O[i][j] *= al;
            #pragma unroll
            for (int j = 0; j < 4; j++) Kt[(tr + i) * 66 + tc + j] = s[i][j];
        }
        __syncthreads();
        #pragma unroll 8
        for (int k2 = 0; k2 < 64; k2++) {
            float pa[4], vb[4];
            #pragma unroll
            for (int i = 0; i < 4; i++) pa[i] = Kt[(tr + i) * 66 + k2];
            #pragma unroll
            for (int j = 0; j < 4; j++) vb[j] = Vs[k2 * 64 + tc + j];
            #pragma unroll
            for (int i = 0; i < 4; i++)
                #pragma unroll
                for (int j = 0; j < 4; j++) O[i][j] = fmaf(pa[i], vb[j], O[i][j]);
        }
    }
    #pragma unroll
    for (int i = 0; i < 4; i++) {
        float inv = 1.f / rl[i];
        int n = q0 + tr + i;
        #pragma unroll
        for (int j = 0; j < 4; j++) {
            int hd = h * DHEAD + tc + j;
            g_xattn[((size_t)b * NN + n) * HID + hd] = f2tf32(O[i][j] * inv);
        }
    }
}

// ---------------- tf32 tensor-core GEMM: C[M,N] = A[M,K] @ B[K,N] ----------------
// 128x128x32 tiles, 256 threads, double-buffered cp.async.
// A,B must already be tf32-rounded. M%128==0, N%128==0, K%32==0.
#define TG_SMEM ((2*128*36 + 2*32*136) * 4)   // 71680 B
__global__ void __launch_bounds__(256) tgemm(const float* __restrict__ A,
                                             const float* __restrict__ B,
                                             float* __restrict__ C,
                                             int M, int N, int K) {
    extern __shared__ float smf[];
    float* As = smf;                 // [2][128][36]
    float* Bs = smf + 2 * 128 * 36;  // [2][32][136]
    const int tid = threadIdx.x;
    const int crow = blockIdx.y * 128;
    const int ccol = blockIdx.x * 128;
    const int lane = tid & 31, wid = tid >> 5;
    const int wm = wid & 1, wn = wid >> 1;       // warp tile: rows wm*64, cols wn*32
    const int g = lane >> 2, tg = lane & 3;

    uint32_t sA = (uint32_t)__cvta_generic_to_shared(As);
    uint32_t sB = (uint32_t)__cvta_generic_to_shared(Bs);

    const int a_r = tid >> 3;           // 0..31
    const int a_c = (tid & 7) * 4;
    const int b_r = tid >> 5;           // 0..7
    const int b_c = (tid & 31) * 4;
    const float* Ag = A + (size_t)(crow + a_r) * K + a_c;
    const float* Bg = B + (size_t)b_r * N + ccol + b_c;

    float acc[4][4][4];
    #pragma unroll
    for (int i = 0; i < 4; i++)
        #pragma unroll
        for (int j = 0; j < 4; j++)
            #pragma unroll
            for (int r = 0; r < 4; r++) acc[i][j][r] = 0.f;

    // prologue: load tile 0 into buf 0
    {
        #pragma unroll
        for (int p = 0; p < 4; p++)
            cp16(sA + (((a_r + p * 32)) * 36 + a_c) * 4, Ag + (size_t)(p * 32) * K);
        #pragma unroll
        for (int p = 0; p < 4; p++)
            cp16(sB + (((b_r + p * 8)) * 136 + b_c) * 4, Bg + (size_t)(p * 8) * N);
        CP_COMMIT();
    }

    const int nk = K >> 5;
    for (int it = 0; it < nk; it++) {
        CP_WAIT0();
        __syncthreads();
        const int buf = it & 1;
        if (it + 1 < nk) {
            const int nb = buf ^ 1;
            const float* Agn = Ag + (size_t)(it + 1) * 32;
            const float* Bgn = Bg + (size_t)(it + 1) * 32 * N;
            #pragma unroll
            for (int p = 0; p < 4; p++)
                cp16(sA + ((nb * 128 + a_r + p * 32) * 36 + a_c) * 4, Agn + (size_t)(p * 32) * K);
            #pragma unroll
            for (int p = 0; p < 4; p++)
                cp16(sB + ((nb * 32 + b_r + p * 8) * 136 + b_c) * 4, Bgn + (size_t)(p * 8) * N);
            CP_COMMIT();
        }
        const float* Ab = As + buf * 128 * 36;
        const float* Bb = Bs + buf * 32 * 136;
        #pragma unroll
        for (int kk = 0; kk < 4; kk++) {
            const int k = kk * 8;
            uint32_t af[4][4];
            #pragma unroll
            for (int mt = 0; mt < 4; mt++) {
                const int rm = wm * 64 + mt * 16;
                af[mt][0] = __float_as_uint(Ab[(rm + g) * 36 + k + tg]);
                af[mt][1] = __float_as_uint(Ab[(rm + g + 8) * 36 + k + tg]);
                af[mt][2] = __float_as_uint(Ab[(rm + g) * 36 + k + tg + 4]);
                af[mt][3] = __float_as_uint(Ab[(rm + g + 8) * 36 + k + tg + 4]);
            }
            uint32_t bf[4][2];
            #pragma unroll
            for (int nt = 0; nt < 4; nt++) {
                const int cn = wn * 32 + nt * 8;
                bf[nt][0] = __float_as_uint(Bb[(k + tg) * 136 + cn + g]);
                bf[nt][1] = __float_as_uint(Bb[(k + tg + 4) * 136 + cn + g]);
            }
            #pragma unroll
            for (int mt = 0; mt < 4; mt++)
                #pragma unroll
                for (int nt = 0; nt < 4; nt++)
                    mma_tf32(acc[mt][nt], af[mt], bf[nt]);
        }
        __syncthreads();
    }

    // epilogue
    #pragma unroll
    for (int mt = 0; mt < 4; mt++) {
        const int r0 = crow + wm * 64 + mt * 16 + g;
        #pragma unroll
        for (int nt = 0; nt < 4; nt++) {
            const int c0 = ccol + wn * 32 + nt * 8 + 2 * tg;
            float2* p0 = (float2*)(C + (size_t)r0 * N + c0);
            float2* p1 = (float2*)(C + (size_t)(r0 + 8) * N + c0);
            *p0 = make_float2(acc[mt][nt][0], acc[mt][nt][1]);
            *p1 = make_float2(acc[mt][nt][2], acc[mt][nt][3]);
        }
    }
}

// ---------------- post-attention ----------------
__global__ void __launch_bounds__(256) post_attn_kernel(const float* __restrict__ x,
                                                        const float* __restrict__ agp) {
    __shared__ float buf[HID];
    __shared__ float red[256];
    const int tid = threadIdx.x;
    const int row = blockIdx.x;
    const int b = row >> 10;
    const float* ar = g_ao + (size_t)row * HID;
    float acc = 0.f;
    for (int k = tid; k < HID; k += 256) { float v = ar[k]; buf[k] = v; acc += v * v; }
    red[tid] = acc; __syncthreads();
    for (int st = 128; st > 0; st >>= 1) { if (tid < st) red[tid] += red[tid + st]; __syncthreads(); }
    float rms = rsqrtf(red[0] * (1.f / HID) + 1e-4f);
    float eg = expf(agp[0]);
    const float* xr = x + (size_t)row * HID;
    float acc2 = 0.f;
    for (int k = tid; k < HID; k += 256) {
        float xa = buf[k] * rms * eg;
        float xm = (0.7f * xr[k] + 0.3f * xa) * MP_ADD_INV;
        g_xmid[(size_t)row * HID + k] = xm;
        buf[k] = xm;
        acc2 += xm * xm;
    }
    __syncthreads();
    red[tid] = acc2; __syncthreads();
    for (int st = 128; st > 0; st >>= 1) { if (tid < st) red[tid] += red[tid + st]; __syncthreads(); }
    float rms2 = rsqrtf(red[0] * (1.f / HID) + 1e-4f);
    const float* gs = g_cond + (size_t)b * 2 * HID;
    for (int k = tid; k < HID; k += 256)
        g_xc2[(size_t)row * HID + k] = f2tf32(buf[k] * rms2 * (1.f + gs[k]) + gs[HID + k]);
}

// ---------------- MLP hidden activation ----------------
__global__ void __launch_bounds__(256) mlp_act_kernel() {
    __shared__ float buf[MLPD];
    __shared__ float red[256];
    const int tid = threadIdx.x;
    const int row = blockIdx.x;
    const float* hr = g_h + (size_t)row * MLPD;
    float acc = 0.f;
    for (int k = tid; k < MLPD; k += 256) { float v = hr[k]; buf[k] = v; acc += v * v; }
    red[tid] = acc; __syncthreads();
    for (int st = 128; st > 0; st >>= 1) { if (tid < st) red[tid] += red[tid + st]; __syncthreads(); }
    float rms = rsqrtf(red[0] * (1.f / MLPD) + 1e-4f);
    for (int k = tid; k < MLPD; k += 256) {
        float u = buf[k] * rms;
        float si = u / (1.f + expf(-u)) * INV_SILU;
        g_h2[(size_t)row * MLPD + k] = f2tf32(si);
    }
}

// ---------------- final ----------------
__global__ void __launch_bounds__(256) final_kernel(const float* __restrict__ mgp,
                                                    float* __restrict__ out) {
    __shared__ float buf[HID];
    __shared__ float red[256];
    const int tid = threadIdx.x;
    const int row = blockIdx.x;
    const float* mr = g_m + (size_t)row * HID;
    float acc = 0.f;
    for (int k = tid; k < HID; k += 256) { float v = mr[k]; buf[k] = v; acc += v * v; }
    red[tid] = acc; __syncthreads();
    for (int st = 128; st > 0; st >>= 1) { if (tid < st) red[tid] += red[tid + st]; __syncthreads(); }
    float rms = rsqrtf(red[0] * (1.f / HID) + 1e-4f);
    float eg = expf(mgp[0]);
    for (int k = tid; k < HID; k += 256) {
        float xm = buf[k] * rms * eg;
        out[(size_t)row * HID + k] = (0.7f * g_xmid[(size_t)row * HID + k] + 0.3f * xm) * MP_ADD_INV;
    }
}

// ---------------- launch ----------------
extern "C" void kernel_launch(void* const* d_in, const int* in_sizes, int n_in,
                              void* d_out, int out_size) {
    (void)in_sizes; (void)n_in; (void)out_size;
    const float* x         = (const float*)d_in[0];
    const float* c         = (const float*)d_in[1];
    const float* w_cond    = (const float*)d_in[2];
    const float* w_qkv     = (const float*)d_in[3];
    const float* w_out     = (const float*)d_in[4];
    const float* w_mlp1    = (const float*)d_in[5];
    const float* w_mlp2    = (const float*)d_in[6];
    const float* attn_gain = (const float*)d_in[7];
    const float* mlp_gain  = (const float*)d_in[8];
    float* out = (float*)d_out;

    void *p_scond, *p_xc1, *p_qkv, *p_xattn, *p_ao, *p_xc2, *p_h, *p_h2, *p_m;
    void *p_wq, *p_wo, *p_wm1, *p_wm2;
    cudaGetSymbolAddress(&p_scond, g_s_cond);
    cudaGetSymbolAddress(&p_xc1,   g_xc1);
    cudaGetSymbolAddress(&p_qkv,   g_qkv);
    cudaGetSymbolAddress(&p_xattn, g_xattn);
    cudaGetSymbolAddress(&p_ao,    g_ao);
    cudaGetSymbolAddress(&p_xc2,   g_xc2);
    cudaGetSymbolAddress(&p_h,     g_h);
    cudaGetSymbolAddress(&p_h2,    g_h2);
    cudaGetSymbolAddress(&p_m,     g_m);
    cudaGetSymbolAddress(&p_wq,    g_wq);
    cudaGetSymbolAddress(&p_wo,    g_wo);
    cudaGetSymbolAddress(&p_wm1,   g_wm1);
    cudaGetSymbolAddress(&p_wm2,   g_wm2);

    cudaFuncSetAttribute(attn_kernel, cudaFuncAttributeMaxDynamicSharedMemorySize, ATT_SMEM);
    cudaFuncSetAttribute(tgemm, cudaFuncAttributeMaxDynamicSharedMemorySize, TG_SMEM);

    // weight preprocessing: row-normalize + scale + tf32 round
    wconv_kernel<<<1024, 256>>>(w_qkv,  (float*)p_wq,  3072, 55.42562584220407f, 32.f);
    wconv_kernel<<<1024, 256>>>(w_out,  (float*)p_wo,  1024, 32.f, 32.f);
    wconv_kernel<<<1024, 256>>>(w_mlp1, (float*)p_wm1, 4096, 64.f, 32.f);
    wconv_kernel<<<4096, 256>>>(w_mlp2, (float*)p_wm2, 1024, 32.f, 64.f);
    rowscale_kernel<<<1024, 256>>>(w_cond, (float*)p_scond, 2048, 45.25483399593904f, 32.f);

    // conditioning -> gain/shift
    cond_act_kernel<<<16, 256>>>(c);
    cond_gemm_kernel<<<8, 256>>>(w_cond);

    // attention branch
    xcond_kernel<<<ROWS, 256>>>(x, (float*)p_xc1);
    tgemm<<<dim3(24, 32), 256, TG_SMEM>>>((const float*)p_xc1, (const float*)p_wq,
                                          (float*)p_qkv, ROWS, 3 * HID, HID);
    qkv_norm_kernel<<<ROWS, 256>>>();
    attn_kernel<<<dim3(16, 64), 256, ATT_SMEM>>>();
    tgemm<<<dim3(8, 32), 256, TG_SMEM>>>((const float*)p_xattn, (const float*)p_wo,
                                         (float*)p_ao, ROWS, HID, HID);
    post_attn_kernel<<<ROWS, 256>>>(x, attn_gain);

    // MLP branch
    tgemm<<<dim3(32, 32), 256, TG_SMEM>>>((const float*)p_xc2, (const float*)p_wm1,
                                          (float*)p_h, ROWS, MLPD, HID);
    mlp_act_kernel<<<ROWS, 256>>>();
    tgemm<<<dim3(8, 32), 256, TG_SMEM>>>((const float*)p_h2, (const float*)p_wm2,
                                         (float*)p_m, ROWS, HID, MLPD);
    final_kernel<<<ROWS, 256>>>(mlp_gain, out);
}

// round 4
// speedup vs baseline: 3.2123x; 1.3574x over previous
#include <cuda_runtime.h>
#include <math.h>
#include <stdint.h>

#define BB 4
#define NN 1024
#define HID 1024
#define NHEADS 16
#define DHEAD 64
#define MLPD 4096
#define ROWS (BB*NN)   // 4096

// ---------------- scratch ----------------
__device__ float g_s_cond[HID];
__device__ float g_ccs[BB*HID];
__device__ float g_cond[BB*2*HID];
__device__ float g_condp[8][4*2048];
__device__ float g_xc1[ROWS*HID];
__device__ float g_qkv[ROWS*3*HID];
__device__ float g_q[ROWS*HID];
__device__ float g_k[ROWS*HID];
__device__ float g_v[ROWS*HID];
__device__ float g_xattn[ROWS*HID];
__device__ float g_ao[ROWS*HID];
__device__ float g_xmid[ROWS*HID];
__device__ float g_xc2[ROWS*HID];
__device__ float g_h[ROWS*MLPD];
__device__ float g_h2[ROWS*MLPD];
__device__ float g_m[ROWS*HID];
__device__ float g_wq[HID*3*HID];
__device__ float g_wo[HID*HID];
__device__ float g_wm1[HID*MLPD];
__device__ float g_wm2[MLPD*HID];

#define MP_ADD_INV 1.3130643285972254f
#define INV_SILU 1.6778523489932886f

__device__ __forceinline__ float f2tf32(float x) {
    uint32_t u;
    asm("cvt.rna.tf32.f32 %0, %1;" : "=r"(u) : "f"(x));
    return __uint_as_float(u);
}

__device__ __forceinline__ void cp16(uint32_t dst, const void* src) {
    asm volatile("cp.async.cg.shared.global [%0], [%1], 16;" :: "r"(dst), "l"(src));
}
#define CP_COMMIT() asm volatile("cp.async.commit_group;")
#define CP_WAIT0()  asm volatile("cp.async.wait_group 0;")

__device__ __forceinline__ void mma_tf32(float* c, const uint32_t* a, const uint32_t* b) {
    asm volatile("mma.sync.aligned.m16n8k8.row.col.f32.tf32.tf32.f32 "
        "{%0,%1,%2,%3}, {%4,%5,%6,%7}, {%8,%9}, {%0,%1,%2,%3};"
        : "+f"(c[0]), "+f"(c[1]), "+f"(c[2]), "+f"(c[3])
        : "r"(a[0]), "r"(a[1]), "r"(a[2]), "r"(a[3]), "r"(b[0]), "r"(b[1]));
}

// ---------------- weight convert ----------------
__global__ void __launch_bounds__(256) wconv_kernel(const float* __restrict__ w,
                                                    float* __restrict__ wt,
                                                    int cols, float alpha, float sqin) {
    __shared__ float red[256];
    const int tid = threadIdx.x;
    const int row = blockIdx.x;
    const float* wr = w + (size_t)row * cols;
    float acc = 0.f;
    for (int j = tid; j < cols; j += 256) { float v = wr[j]; acc += v * v; }
    red[tid] = acc; __syncthreads();
    for (int st = 128; st > 0; st >>= 1) { if (tid < st) red[tid] += red[tid + st]; __syncthreads(); }
    float s = 1.f / ((sqrtf(red[0]) * alpha + 1e-4f) * sqin);
    float* wo = wt + (size_t)row * cols;
    for (int j = tid; j < cols; j += 256) wo[j] = f2tf32(wr[j] * s);
}

__global__ void __launch_bounds__(256) rowscale_kernel(const float* __restrict__ w,
                                                       float* __restrict__ s,
                                                       int cols, float alpha, float sqin) {
    __shared__ float red[256];
    const int tid = threadIdx.x;
    const int row = blockIdx.x;
    const float* wr = w + (size_t)row * cols;
    float acc = 0.f;
    for (int j = tid; j < cols; j += 256) { float v = wr[j]; acc += v * v; }
    red[tid] = acc; __syncthreads();
    for (int st = 128; st > 0; st >>= 1) { if (tid < st) red[tid] += red[tid + st]; __syncthreads(); }
    if (tid == 0) s[row] = 1.f / ((sqrtf(red[0]) * alpha + 1e-4f) * sqin);
}

// ---------------- conditioning ----------------
__global__ void __launch_bounds__(256) cond_act_kernel(const float* __restrict__ c) {
    int idx = blockIdx.x * 256 + threadIdx.x;
    float v = c[idx];
    float si = v / (1.f + expf(-v)) * INV_SILU;
    g_ccs[idx] = si * g_s_cond[idx & (HID - 1)];
}

// split-K: grid (8 jblocks, 8 ksplits), partials to g_condp
__global__ void __launch_bounds__(256) cond_gemm_part(const float* __restrict__ w) {
    __shared__ float cs[4 * 128];
    const int tid = threadIdx.x;
    const int jb = blockIdx.x, ks = blockIdx.y;
    const int k0 = ks * 128;
    for (int t = tid; t < 512; t += 256) {
        int bidx = t >> 7, kk = t & 127;
        cs[t] = g_ccs[bidx * HID + k0 + kk];
    }
    __syncthreads();
    int j = jb * 256 + tid;
    float a0 = 0.f, a1 = 0.f, a2 = 0.f, a3 = 0.f;
    for (int kk = 0; kk < 128; kk++) {
        float wv = w[(size_t)(k0 + kk) * (2 * HID) + j];
        a0 = fmaf(cs[kk], wv, a0);
        a1 = fmaf(cs[128 + kk], wv, a1);
        a2 = fmaf(cs[256 + kk], wv, a2);
        a3 = fmaf(cs[384 + kk], wv, a3);
    }
    g_condp[ks][0 * 2048 + j] = a0;
    g_condp[ks][1 * 2048 + j] = a1;
    g_condp[ks][2 * 2048 + j] = a2;
    g_condp[ks][3 * 2048 + j] = a3;
}

__global__ void __launch_bounds__(256) cond_gemm_reduce() {
    int i = blockIdx.x * 256 + threadIdx.x;   // 8192 = [4][2048]
    float s = 0.f;
    #pragma unroll
    for (int ks = 0; ks < 8; ks++) s += g_condp[ks][i];
    g_cond[i] = s;
}

// ---------------- xcond ----------------
__global__ void __launch_bounds__(256) xcond_kernel(const float* __restrict__ x,
                                                    float* __restrict__ out) {
    __shared__ float buf[HID];
    __shared__ float red[256];
    const int tid = threadIdx.x;
    const int row = blockIdx.x;
    const int b = row >> 10;
    const float* xr = x + (size_t)row * HID;
    float acc = 0.f;
    for (int k = tid; k < HID; k += 256) { float v = xr[k]; buf[k] = v; acc += v * v; }
    red[tid] = acc; __syncthreads();
    for (int st = 128; st > 0; st >>= 1) { if (tid < st) red[tid] += red[tid + st]; __syncthreads(); }
    float rms = rsqrtf(red[0] * (1.f / HID) + 1e-4f);
    const float* gs = g_cond + (size_t)b * 2 * HID;
    for (int k = tid; k < HID; k += 256)
        out[(size_t)row * HID + k] = f2tf32(buf[k] * rms * (1.f + gs[k]) + gs[HID + k]);
}

// ---------------- qkv normalize + head split (tf32-rounded outputs) ----------------
__global__ void __launch_bounds__(256) qkv_norm_kernel() {
    __shared__ float buf[3 * HID];
    __shared__ float red[768];
    __shared__ float hs[32];
    const int tid = threadIdx.x;
    const int row = blockIdx.x;
    const float* qr = g_qkv + (size_t)row * 3 * HID;
    float aq = 0.f, ak = 0.f, av = 0.f;
    for (int k = tid; k < HID; k += 256) {
        float a = qr[k];           buf[k] = a;           aq += a * a;
        float bq = qr[HID + k];    buf[HID + k] = bq;    ak += bq * bq;
        float cv = qr[2*HID + k];  buf[2*HID + k] = cv;  av += cv * cv;
    }
    red[tid] = aq; red[256 + tid] = ak; red[512 + tid] = av; __syncthreads();
    for (int st = 128; st > 0; st >>= 1) {
        if (tid < st) {
            red[tid] += red[tid + st];
            red[256 + tid] += red[256 + tid + st];
            red[512 + tid] += red[512 + tid + st];
        }
        __syncthreads();
    }
    float rq = rsqrtf(red[0]   * (1.f / HID) + 1e-4f);
    float rk = rsqrtf(red[256] * (1.f / HID) + 1e-4f);
    float rv = rsqrtf(red[512] * (1.f / HID) + 1e-4f);
    __syncthreads();
    for (int k = tid; k < HID; k += 256) {
        buf[k] *= rq; buf[HID + k] *= rk; buf[2*HID + k] *= rv;
    }
    __syncthreads();
    if (tid < 32) {
        int hh = tid & 15;
        int base = ((tid >> 4) ? HID : 0) + hh * DHEAD;
        float s = 0.f;
        #pragma unroll
        for (int d = 0; d < DHEAD; d++) { float v = buf[base + d]; s += v * v; }
        hs[tid] = rsqrtf(s + 1e-6f);
    }
    __syncthreads();
    const int b = row >> 10, n = row & (NN - 1);
    for (int k = tid; k < HID; k += 256) {
        int hh = k >> 6, d = k & 63;
        size_t o = ((size_t)(b * NHEADS + hh) * NN + n) * DHEAD + d;
        g_q[o] = f2tf32(buf[k] * hs[hh]);
        g_k[o] = f2tf32(buf[HID + k] * hs[16 + hh]);
        g_v[o] = f2tf32(buf[2*HID + k]);
    }
}

// ---------------- attention on tf32 tensor cores ----------------
// Per CTA: 128 q rows of one (b,h); 16 KV tiles of 64.
// Scores |s| <= 0.125 (unit-norm q,k / 8) -> no max subtraction needed.
#define ATT_SMEM ((64*68 + 64*68 + 128*68) * 4)   // 69632 B
__global__ void __launch_bounds__(256) attn_mma_kernel() {
    extern __shared__ float sm[];
    float* Ks = sm;               // [64 kv][68]
    float* Vs = sm + 64 * 68;     // [64 kv][68]
    float* Ps = sm + 2 * 64 * 68; // [128 q][68]
    const int tid = threadIdx.x;
    const int lane = tid & 31, w = tid >> 5;
    const int g = lane >> 2, tg = lane & 3;
    const int bh = blockIdx.y, q0 = blockIdx.x * 128;
    const int b = bh >> 4, h = bh & 15;
    const float* Qg = g_q + (size_t)bh * (NN * DHEAD);
    const float* Kg = g_k + (size_t)bh * (NN * DHEAD);
    const float* Vg = g_v + (size_t)bh * (NN * DHEAD);

    // persistent Q fragments (fold 1/sqrt(DH)=0.125; exact power of 2 keeps tf32)
    uint32_t qf[8][4];
    {
        const int r0 = q0 + w * 16;
        #pragma unroll
        for (int kk = 0; kk < 8; kk++) {
            qf[kk][0] = __float_as_uint(Qg[(size_t)(r0 + g) * 64 + kk * 8 + tg] * 0.125f);
            qf[kk][1] = __float_as_uint(Qg[(size_t)(r0 + g + 8) * 64 + kk * 8 + tg] * 0.125f);
            qf[kk][2] = __float_as_uint(Qg[(size_t)(r0 + g) * 64 + kk * 8 + tg + 4] * 0.125f);
            qf[kk][3] = __float_as_uint(Qg[(size_t)(r0 + g + 8) * 64 + kk * 8 + tg + 4] * 0.125f);
        }
    }

    float Of[8][4];
    #pragma unroll
    for (int nt = 0; nt < 8; nt++)
        #pragma unroll
        for (int r = 0; r < 4; r++) Of[nt][r] = 0.f;
    float rs0 = 0.f, rs1 = 0.f;

    const int pr = w * 16;
    for (int kt = 0; kt < 16; kt++) {
        __syncthreads();
        for (int t4 = tid; t4 < 1024; t4 += 256) {
            int r = t4 >> 4, c = (t4 & 15) * 4;
            *(float4*)&Ks[r * 68 + c] = *(const float4*)(Kg + (size_t)kt * 4096 + r * 64 + c);
            *(float4*)&Vs[r * 68 + c] = *(const float4*)(Vg + (size_t)kt * 4096 + r * 64 + c);
        }
        __syncthreads();
        // S = Q K^T  (per warp: 16 q x 64 kv), exp, rowsum, P -> smem
        #pragma unroll
        for (int nt = 0; nt < 8; nt++) {
            float sc[4] = {0.f, 0.f, 0.f, 0.f};
            #pragma unroll
            for (int kk = 0; kk < 8; kk++) {
                uint32_t bb[2];
                bb[0] = __float_as_uint(Ks[(nt * 8 + g) * 68 + kk * 8 + tg]);
                bb[1] = __float_as_uint(Ks[(nt * 8 + g) * 68 + kk * 8 + tg + 4]);
                mma_tf32(sc, qf[kk], bb);
            }
            float e0 = __expf(sc[0]), e1 = __expf(sc[1]);
            float e2 = __expf(sc[2]), e3 = __expf(sc[3]);
            rs0 += e0 + e1; rs1 += e2 + e3;
            *(float2*)&Ps[(pr + g) * 68 + nt * 8 + 2 * tg]     = make_float2(f2tf32(e0), f2tf32(e1));
            *(float2*)&Ps[(pr + g + 8) * 68 + nt * 8 + 2 * tg] = make_float2(f2tf32(e2), f2tf32(e3));
        }
        __syncwarp();
        // O += P V  (per warp reads only its own P slice)
        #pragma unroll
        for (int kk = 0; kk < 8; kk++) {
            uint32_t af[4];
            af[0] = __float_as_uint(Ps[(pr + g) * 68 + kk * 8 + tg]);
            af[1] = __float_as_uint(Ps[(pr + g + 8) * 68 + kk * 8 + tg]);
            af[2] = __float_as_uint(Ps[(pr + g) * 68 + kk * 8 + tg + 4]);
            af[3] = __float_as_uint(Ps[(pr + g + 8) * 68 + kk * 8 + tg + 4]);
            #pragma unroll
            for (int nt = 0; nt < 8; nt++) {
                uint32_t bb[2];
                bb[0] = __float_as_uint(Vs[(kk * 8 + tg) * 68 + nt * 8 + g]);
                bb[1] = __float_as_uint(Vs[(kk * 8 + tg + 4) * 68 + nt * 8 + g]);
                mma_tf32(Of[nt], af, bb);
            }
        }
    }

    // rowsum reduce across the 4 tg lanes of each row group
    rs0 += __shfl_xor_sync(0xffffffffu, rs0, 1);
    rs0 += __shfl_xor_sync(0xffffffffu, rs0, 2);
    rs1 += __shfl_xor_sync(0xffffffffu, rs1, 1);
    rs1 += __shfl_xor_sync(0xffffffffu, rs1, 2);
    float inv0 = 1.f / rs0, inv1 = 1.f / rs1;

    const int n0 = q0 + w * 16 + g;
    #pragma unroll
    for (int nt = 0; nt < 8; nt++) {
        int col = h * 64 + nt * 8 + 2 * tg;
        float* p0 = g_xattn + ((size_t)b * NN + n0) * HID + col;
        float* p1 = g_xattn + ((size_t)b * NN + n0 + 8) * HID + col;
        *(float2*)p0 = make_float2(f2tf32(Of[nt][0] * inv0), f2tf32(Of[nt][1] * inv0));
        *(float2*)p1 = make_float2(f2tf32(Of[nt][2] * inv1), f2tf32(Of[nt][3] * inv1));
    }
}

// ---------------- tf32 tensor-core GEMM ----------------
#define TG_SMEM ((2*128*36 + 2*32*136) * 4)
__global__ void __launch_bounds__(256) tgemm(const float* __restrict__ A,
                                             const float* __restrict__ B,
                                             float* __restrict__ C,
                                             int M, int N, int K) {
    extern __shared__ float smf[];
    float* As = smf;
    float* Bs = smf + 2 * 128 * 36;
    const int tid = threadIdx.x;
    const int crow = blockIdx.y * 128;
    const int ccol = blockIdx.x * 128;
    const int lane = tid & 31, wid = tid >> 5;
    const int wm = wid & 1, wn = wid >> 1;
    const int g = lane >> 2, tg = lane & 3;

    uint32_t sA = (uint32_t)__cvta_generic_to_shared(As);
    uint32_t sB = (uint32_t)__cvta_generic_to_shared(Bs);

    const int a_r = tid >> 3;
    const int a_c = (tid & 7) * 4;
    const int b_r = tid >> 5;
    const int b_c = (tid & 31) * 4;
    const float* Ag = A + (size_t)(crow + a_r) * K + a_c;
    const float* Bg = B + (size_t)b_r * N + ccol + b_c;

    float acc[4][4][4];
    #pragma unroll
    for (int i = 0; i < 4; i++)
        #pragma unroll
        for (int j = 0; j < 4; j++)
            #pragma unroll
            for (int r = 0; r < 4; r++) acc[i][j][r] = 0.f;

    {
        #pragma unroll
        for (int p = 0; p < 4; p++)
            cp16(sA + (((a_r + p * 32)) * 36 + a_c) * 4, Ag + (size_t)(p * 32) * K);
        #pragma unroll
        for (int p = 0; p < 4; p++)
            cp16(sB + (((b_r + p * 8)) * 136 + b_c) * 4, Bg + (size_t)(p * 8) * N);
        CP_COMMIT();
    }

    const int nk = K >> 5;
    for (int it = 0; it < nk; it++) {
        CP_WAIT0();
        __syncthreads();
        const int buf = it & 1;
        if (it + 1 < nk) {
            const int nb = buf ^ 1;
            const float* Agn = Ag + (size_t)(it + 1) * 32;
            const float* Bgn = Bg + (size_t)(it + 1) * 32 * N;
            #pragma unroll
            for (int p = 0; p < 4; p++)
                cp16(sA + ((nb * 128 + a_r + p * 32) * 36 + a_c) * 4, Agn + (size_t)(p * 32) * K);
            #pragma unroll
            for (int p = 0; p < 4; p++)
                cp16(sB + ((nb * 32 + b_r + p * 8) * 136 + b_c) * 4, Bgn + (size_t)(p * 8) * N);
            CP_COMMIT();
        }
        const float* Ab = As + buf * 128 * 36;
        const float* Bb = Bs + buf * 32 * 136;
        #pragma unroll
        for (int kk = 0; kk < 4; kk++) {
            const int k = kk * 8;
            uint32_t af[4][4];
            #pragma unroll
            for (int mt = 0; mt < 4; mt++) {
                const int rm = wm * 64 + mt * 16;
                af[mt][0] = __float_as_uint(Ab[(rm + g) * 36 + k + tg]);
                af[mt][1] = __float_as_uint(Ab[(rm + g + 8) * 36 + k + tg]);
                af[mt][2] = __float_as_uint(Ab[(rm + g) * 36 + k + tg + 4]);
                af[mt][3] = __float_as_uint(Ab[(rm + g + 8) * 36 + k + tg + 4]);
            }
            uint32_t bf[4][2];
            #pragma unroll
            for (int nt = 0; nt < 4; nt++) {
                const int cn = wn * 32 + nt * 8;
                bf[nt][0] = __float_as_uint(Bb[(k + tg) * 136 + cn + g]);
                bf[nt][1] = __float_as_uint(Bb[(k + tg + 4) * 136 + cn + g]);
            }
            #pragma unroll
            for (int mt = 0; mt < 4; mt++)
                #pragma unroll
                for (int nt = 0; nt < 4; nt++)
                    mma_tf32(acc[mt][nt], af[mt], bf[nt]);
        }
        __syncthreads();
    }

    #pragma unroll
    for (int mt = 0; mt < 4; mt++) {
        const int r0 = crow + wm * 64 + mt * 16 + g;
        #pragma unroll
        for (int nt = 0; nt < 4; nt++) {
            const int c0 = ccol + wn * 32 + nt * 8 + 2 * tg;
            float2* p0 = (float2*)(C + (size_t)r0 * N + c0);
            float2* p1 = (float2*)(C + (size_t)(r0 + 8) * N + c0);
            *p0 = make_float2(acc[mt][nt][0], acc[mt][nt][1]);
            *p1 = make_float2(acc[mt][nt][2], acc[mt][nt][3]);
        }
    }
}

// ---------------- post-attention ----------------
__global__ void __launch_bounds__(256) post_attn_kernel(const float* __restrict__ x,
                                                        const float* __restrict__ agp) {
    __shared__ float buf[HID];
    __shared__ float red[256];
    const int tid = threadIdx.x;
    const int row = blockIdx.x;
    const int b = row >> 10;
    const float* ar = g_ao + (size_t)row * HID;
    float acc = 0.f;
    for (int k = tid; k < HID; k += 256) { float v = ar[k]; buf[k] = v; acc += v * v; }
    red[tid] = acc; __syncthreads();
    for (int st = 128; st > 0; st >>= 1) { if (tid < st) red[tid] += red[tid + st]; __syncthreads(); }
    float rms = rsqrtf(red[0] * (1.f / HID) + 1e-4f);
    float eg = expf(agp[0]);
    const float* xr = x + (size_t)row * HID;
    float acc2 = 0.f;
    for (int k = tid; k < HID; k += 256) {
        float xa = buf[k] * rms * eg;
        float xm = (0.7f * xr[k] + 0.3f * xa) * MP_ADD_INV;
        g_xmid[(size_t)row * HID + k] = xm;
        buf[k] = xm;
        acc2 += xm * xm;
    }
    __syncthreads();
    red[tid] = acc2; __syncthreads();
    for (int st = 128; st > 0; st >>= 1) { if (tid < st) red[tid] += red[tid + st]; __syncthreads(); }
    float rms2 = rsqrtf(red[0] * (1.f / HID) + 1e-4f);
    const float* gs = g_cond + (size_t)b * 2 * HID;
    for (int k = tid; k < HID; k += 256)
        g_xc2[(size_t)row * HID + k] = f2tf32(buf[k] * rms2 * (1.f + gs[k]) + gs[HID + k]);
}

// ---------------- MLP hidden activation ----------------
__global__ void __launch_bounds__(256) mlp_act_kernel() {
    __shared__ float buf[MLPD];
    __shared__ float red[256];
    const int tid = threadIdx.x;
    const int row = blockIdx.x;
    const float* hr = g_h + (size_t)row * MLPD;
    float acc = 0.f;
    for (int k = tid; k < MLPD; k += 256) { float v = hr[k]; buf[k] = v; acc += v * v; }
    red[tid] = acc; __syncthreads();
    for (int st = 128; st > 0; st >>= 1) { if (tid < st) red[tid] += red[tid + st]; __syncthreads(); }
    float rms = rsqrtf(red[0] * (1.f / MLPD) + 1e-4f);
    for (int k = tid; k < MLPD; k += 256) {
        float u = buf[k] * rms;
        float si = u / (1.f + expf(-u)) * INV_SILU;
        g_h2[(size_t)row * MLPD + k] = f2tf32(si);
    }
}

// ---------------- final ----------------
__global__ void __launch_bounds__(256) final_kernel(const float* __restrict__ mgp,
                                                    float* __restrict__ out) {
    __shared__ float buf[HID];
    __shared__ float red[256];
    const int tid = threadIdx.x;
    const int row = blockIdx.x;
    const float* mr = g_m + (size_t)row * HID;
    float acc = 0.f;
    for (int k = tid; k < HID; k += 256) { float v = mr[k]; buf[k] = v; acc += v * v; }
    red[tid] = acc; __syncthreads();
    for (int st = 128; st > 0; st >>= 1) { if (tid < st) red[tid] += red[tid + st]; __syncthreads(); }
    float rms = rsqrtf(red[0] * (1.f / HID) + 1e-4f);
    float eg = expf(mgp[0]);
    for (int k = tid; k < HID; k += 256) {
        float xm = buf[k] * rms * eg;
        out[(size_t)row * HID + k] = (0.7f * g_xmid[(size_t)row * HID + k] + 0.3f * xm) * MP_ADD_INV;
    }
}

// ---------------- launch ----------------
extern "C" void kernel_launch(void* const* d_in, const int* in_sizes, int n_in,
                              void* d_out, int out_size) {
    (void)in_sizes; (void)n_in; (void)out_size;
    const float* x         = (const float*)d_in[0];
    const float* c         = (const float*)d_in[1];
    const float* w_cond    = (const float*)d_in[2];
    const float* w_qkv     = (const float*)d_in[3];
    const float* w_out     = (const float*)d_in[4];
    const float* w_mlp1    = (const float*)d_in[5];
    const float* w_mlp2    = (const float*)d_in[6];
    const float* attn_gain = (const float*)d_in[7];
    const float* mlp_gain  = (const float*)d_in[8];
    float* out = (float*)d_out;

    void *p_scond, *p_xc1, *p_qkv, *p_xattn, *p_ao, *p_xc2, *p_h, *p_h2, *p_m;
    void *p_wq, *p_wo, *p_wm1, *p_wm2;
    cudaGetSymbolAddress(&p_scond, g_s_cond);
    cudaGetSymbolAddress(&p_xc1,   g_xc1);
    cudaGetSymbolAddress(&p_qkv,   g_qkv);
    cudaGetSymbolAddress(&p_xattn, g_xattn);
    cudaGetSymbolAddress(&p_ao,    g_ao);
    cudaGetSymbolAddress(&p_xc2,   g_xc2);
    cudaGetSymbolAddress(&p_h,     g_h);
    cudaGetSymbolAddress(&p_h2,    g_h2);
    cudaGetSymbolAddress(&p_m,     g_m);
    cudaGetSymbolAddress(&p_wq,    g_wq);
    cudaGetSymbolAddress(&p_wo,    g_wo);
    cudaGetSymbolAddress(&p_wm1,   g_wm1);
    cudaGetSymbolAddress(&p_wm2,   g_wm2);

    cudaFuncSetAttribute(attn_mma_kernel, cudaFuncAttributeMaxDynamicSharedMemorySize, ATT_SMEM);
    cudaFuncSetAttribute(tgemm, cudaFuncAttributeMaxDynamicSharedMemorySize, TG_SMEM);

    // weight preprocessing
    wconv_kernel<<<1024, 256>>>(w_qkv,  (float*)p_wq,  3072, 55.42562584220407f, 32.f);
    wconv_kernel<<<1024, 256>>>(w_out,  (float*)p_wo,  1024, 32.f, 32.f);
    wconv_kernel<<<1024, 256>>>(w_mlp1, (float*)p_wm1, 4096, 64.f, 32.f);
    wconv_kernel<<<4096, 256>>>(w_mlp2, (float*)p_wm2, 1024, 32.f, 64.f);
    rowscale_kernel<<<1024, 256>>>(w_cond, (float*)p_scond, 2048, 45.25483399593904f, 32.f);

    // conditioning
    cond_act_kernel<<<16, 256>>>(c);
    cond_gemm_part<<<dim3(8, 8), 256>>>(w_cond);
    cond_gemm_reduce<<<32, 256>>>();

    // attention branch
    xcond_kernel<<<ROWS, 256>>>(x, (float*)p_xc1);
    tgemm<<<dim3(24, 32), 256, TG_SMEM>>>((const float*)p_xc1, (const float*)p_wq,
                                          (float*)p_qkv, ROWS, 3 * HID, HID);
    qkv_norm_kernel<<<ROWS, 256>>>();
    attn_mma_kernel<<<dim3(8, 64), 256, ATT_SMEM>>>();
    tgemm<<<dim3(8, 32), 256, TG_SMEM>>>((const float*)p_xattn, (const float*)p_wo,
                                         (float*)p_ao, ROWS, HID, HID);
    post_attn_kernel<<<ROWS, 256>>>(x, attn_gain);

    // MLP branch
    tgemm<<<dim3(32, 32), 256, TG_SMEM>>>((const float*)p_xc2, (const float*)p_wm1,
                                          (float*)p_h, ROWS, MLPD, HID);
    mlp_act_kernel<<<ROWS, 256>>>();
    tgemm<<<dim3(8, 32), 256, TG_SMEM>>>((const float*)p_h2, (const float*)p_wm2,
                                         (float*)p_m, ROWS, HID, MLPD);
    final_kernel<<<ROWS, 256>>>(mlp_gain, out);
}

// round 10
// speedup vs baseline: 5.3249x; 1.6576x over previous
#include <cuda_runtime.h>
#include <cuda_fp16.h>
#include <math.h>
#include <stdint.h>

#define BB 4
#define NN 1024
#define HID 1024
#define NHEADS 16
#define DHEAD 64
#define MLPD 4096
#define ROWS (BB*NN)   // 4096

// ---------------- scratch ----------------
__device__ float g_s_cond[HID];
__device__ float g_ccs[BB*HID];
__device__ float g_cond[BB*2*HID];
__device__ float g_condp[8][4*2048];
__device__ __half g_xc1h[ROWS*HID];
__device__ float g_qkv[ROWS*3*HID];
__device__ __half g_qh[ROWS*HID];
__device__ __half g_kh[ROWS*HID];
__device__ __half g_vh[ROWS*HID];
__device__ __half g_xattnh[ROWS*HID];
__device__ float g_ao[ROWS*HID];
__device__ float g_xmid[ROWS*HID];
__device__ __half g_xc2h[ROWS*HID];
__device__ float g_h[ROWS*MLPD];
__device__ __half g_h2h[ROWS*MLPD];
__device__ float g_m[ROWS*HID];
// fp16 pre-scaled weights (x1024; GEMM epilogue multiplies by 1/1024)
__device__ __half g_wqh[HID*3*HID];
__device__ __half g_woh[HID*HID];
__device__ __half g_wm1h[HID*MLPD];
__device__ __half g_wm2h[MLPD*HID];

#define MP_ADD_INV 1.3130643285972254f
#define INV_SILU 1.6778523489932886f
#define OUTSCALE 0.0009765625f   // 1/1024

__device__ __forceinline__ uint32_t h2_as_u32(__half2 v) {
    union { __half2 h; uint32_t u; } cvt;
    cvt.h = v;
    return cvt.u;
}

__device__ __forceinline__ void cp16(uint32_t dst, const void* src) {
    asm volatile("cp.async.cg.shared.global [%0], [%1], 16;" :: "r"(dst), "l"(src));
}
#define CP_COMMIT() asm volatile("cp.async.commit_group;")
#define CP_WAIT0()  asm volatile("cp.async.wait_group 0;")

__device__ __forceinline__ void mma_f16(float* c, const uint32_t* a, const uint32_t* b) {
    asm volatile("mma.sync.aligned.m16n8k16.row.col.f32.f16.f16.f32 "
        "{%0,%1,%2,%3}, {%4,%5,%6,%7}, {%8,%9}, {%0,%1,%2,%3};"
        : "+f"(c[0]), "+f"(c[1]), "+f"(c[2]), "+f"(c[3])
        : "r"(a[0]), "r"(a[1]), "r"(a[2]), "r"(a[3]), "r"(b[0]), "r"(b[1]));
}
__device__ __forceinline__ void ldsm4(uint32_t* r, uint32_t addr) {
    asm volatile("ldmatrix.sync.aligned.m8n8.x4.shared.b16 {%0,%1,%2,%3}, [%4];"
        : "=r"(r[0]), "=r"(r[1]), "=r"(r[2]), "=r"(r[3]) : "r"(addr));
}
__device__ __forceinline__ void ldsm2(uint32_t* r, uint32_t addr) {
    asm volatile("ldmatrix.sync.aligned.m8n8.x2.shared.b16 {%0,%1}, [%2];"
        : "=r"(r[0]), "=r"(r[1]) : "r"(addr));
}
__device__ __forceinline__ void ldsm2t(uint32_t* r, uint32_t addr) {
    asm volatile("ldmatrix.sync.aligned.m8n8.x2.trans.shared.b16 {%0,%1}, [%2];"
        : "=r"(r[0]), "=r"(r[1]) : "r"(addr));
}

// ---------------- weight convert: row-normalize + scale*1024 -> fp16 ----------------
__global__ void __launch_bounds__(256) wconv_h(const float* __restrict__ w,
                                               __half* __restrict__ wt,
                                               int cols, float alpha, float sqin) {
    __shared__ float red[256];
    const int tid = threadIdx.x;
    const int row = blockIdx.x;
    const float* wr = w + (size_t)row * cols;
    float acc = 0.f;
    for (int j = tid; j < cols; j += 256) { float v = wr[j]; acc += v * v; }
    red[tid] = acc; __syncthreads();
    for (int st = 128; st > 0; st >>= 1) { if (tid < st) red[tid] += red[tid + st]; __syncthreads(); }
    float s = 1024.f / ((sqrtf(red[0]) * alpha + 1e-4f) * sqin);
    __half* wo = wt + (size_t)row * cols;
    for (int j = tid; j < cols; j += 256) wo[j] = __float2half_rn(wr[j] * s);
}

__global__ void __launch_bounds__(256) rowscale_kernel(const float* __restrict__ w,
                                                       float* __restrict__ s,
                                                       int cols, float alpha, float sqin) {
    __shared__ float red[256];
    const int tid = threadIdx.x;
    const int row = blockIdx.x;
    const float* wr = w + (size_t)row * cols;
    float acc = 0.f;
    for (int j = tid; j < cols; j += 256) { float v = wr[j]; acc += v * v; }
    red[tid] = acc; __syncthreads();
    for (int st = 128; st > 0; st >>= 1) { if (tid < st) red[tid] += red[tid + st]; __syncthreads(); }
    if (tid == 0) s[row] = 1.f / ((sqrtf(red[0]) * alpha + 1e-4f) * sqin);
}

// ---------------- conditioning (fp32 path) ----------------
__global__ void __launch_bounds__(256) cond_act_kernel(const float* __restrict__ c) {
    int idx = blockIdx.x * 256 + threadIdx.x;
    float v = c[idx];
    float si = v / (1.f + expf(-v)) * INV_SILU;
    g_ccs[idx] = si * g_s_cond[idx & (HID - 1)];
}

__global__ void __launch_bounds__(256) cond_gemm_part(const float* __restrict__ w) {
    __shared__ float cs[4 * 128];
    const int tid = threadIdx.x;
    const int jb = blockIdx.x, ks = blockIdx.y;
    const int k0 = ks * 128;
    for (int t = tid; t < 512; t += 256) {
        int bidx = t >> 7, kk = t & 127;
        cs[t] = g_ccs[bidx * HID + k0 + kk];
    }
    __syncthreads();
    int j = jb * 256 + tid;
    float a0 = 0.f, a1 = 0.f, a2 = 0.f, a3 = 0.f;
    for (int kk = 0; kk < 128; kk++) {
        float wv = w[(size_t)(k0 + kk) * (2 * HID) + j];
        a0 = fmaf(cs[kk], wv, a0);
        a1 = fmaf(cs[128 + kk], wv, a1);
        a2 = fmaf(cs[256 + kk], wv, a2);
        a3 = fmaf(cs[384 + kk], wv, a3);
    }
    g_condp[ks][0 * 2048 + j] = a0;
    g_condp[ks][1 * 2048 + j] = a1;
    g_condp[ks][2 * 2048 + j] = a2;
    g_condp[ks][3 * 2048 + j] = a3;
}

__global__ void __launch_bounds__(256) cond_gemm_reduce() {
    int i = blockIdx.x * 256 + threadIdx.x;
    float s = 0.f;
    #pragma unroll
    for (int ks = 0; ks < 8; ks++) s += g_condp[ks][i];
    g_cond[i] = s;
}

// ---------------- xcond -> fp16 ----------------
__global__ void __launch_bounds__(256) xcond_kernel(const float* __restrict__ x,
                                                    __half* __restrict__ out) {
    __shared__ float buf[HID];
    __shared__ float red[256];
    const int tid = threadIdx.x;
    const int row = blockIdx.x;
    const int b = row >> 10;
    const float* xr = x + (size_t)row * HID;
    float acc = 0.f;
    for (int k = tid; k < HID; k += 256) { float v = xr[k]; buf[k] = v; acc += v * v; }
    red[tid] = acc; __syncthreads();
    for (int st = 128; st > 0; st >>= 1) { if (tid < st) red[tid] += red[tid + st]; __syncthreads(); }
    float rms = rsqrtf(red[0] * (1.f / HID) + 1e-4f);
    const float* gs = g_cond + (size_t)b * 2 * HID;
    for (int k = tid; k < HID; k += 256)
        out[(size_t)row * HID + k] = __float2half_rn(buf[k] * rms * (1.f + gs[k]) + gs[HID + k]);
}

// ---------------- qkv normalize + head split -> fp16 (q pre-scaled 0.125) ----------------
__global__ void __launch_bounds__(256) qkv_norm_kernel() {
    __shared__ float buf[3 * HID];
    __shared__ float red[768];
    __shared__ float hs[32];
    const int tid = threadIdx.x;
    const int row = blockIdx.x;
    const float* qr = g_qkv + (size_t)row * 3 * HID;
    float aq = 0.f, ak = 0.f, av = 0.f;
    for (int k = tid; k < HID; k += 256) {
        float a = qr[k];           buf[k] = a;           aq += a * a;
        float bq = qr[HID + k];    buf[HID + k] = bq;    ak += bq * bq;
        float cv = qr[2*HID + k];  buf[2*HID + k] = cv;  av += cv * cv;
    }
    red[tid] = aq; red[256 + tid] = ak; red[512 + tid] = av; __syncthreads();
    for (int st = 128; st > 0; st >>= 1) {
        if (tid < st) {
            red[tid] += red[tid + st];
            red[256 + tid] += red[256 + tid + st];
            red[512 + tid] += red[512 + tid + st];
        }
        __syncthreads();
    }
    float rq = rsqrtf(red[0]   * (1.f / HID) + 1e-4f);
    float rk = rsqrtf(red[256] * (1.f / HID) + 1e-4f);
    float rv = rsqrtf(red[512] * (1.f / HID) + 1e-4f);
    __syncthreads();
    for (int k = tid; k < HID; k += 256) {
        buf[k] *= rq; buf[HID + k] *= rk; buf[2*HID + k] *= rv;
    }
    __syncthreads();
    if (tid < 32) {
        int hh = tid & 15;
        int base = ((tid >> 4) ? HID : 0) + hh * DHEAD;
        float s = 0.f;
        #pragma unroll
        for (int d = 0; d < DHEAD; d++) { float v = buf[base + d]; s += v * v; }
        hs[tid] = rsqrtf(s + 1e-6f);
    }
    __syncthreads();
    const int b = row >> 10, n = row & (NN - 1);
    for (int k = tid; k < HID; k += 256) {
        int hh = k >> 6, d = k & 63;
        size_t o = ((size_t)(b * NHEADS + hh) * NN + n) * DHEAD + d;
        g_qh[o] = __float2half_rn(buf[k] * hs[hh] * 0.125f);
        g_kh[o] = __float2half_rn(buf[HID + k] * hs[16 + hh]);
        g_vh[o] = __float2half_rn(buf[2*HID + k]);
    }
}

// ---------------- fp16 flash attention (no max track; P stays in registers) ----------------
// SMEM: Ks[2][64][72], Vs[2][64][72] halves = 73728 B
#define ATTH_SMEM (2*(64*72 + 64*72)*2)
__global__ void __launch_bounds__(256) attn_h_kernel() {
    extern __shared__ __half smh[];
    __half* Ks = smh;                 // [2][64][72]
    __half* Vs = smh + 2 * 64 * 72;   // [2][64][72]
    const int tid = threadIdx.x;
    const int lane = tid & 31, w = tid >> 5;
    const int g = lane >> 2, tg = lane & 3;
    const int bh = blockIdx.y, q0 = blockIdx.x * 128;
    const int b = bh >> 4, h = bh & 15;
    const __half* Qg = g_qh + (size_t)bh * (NN * DHEAD);
    const __half* Kg = g_kh + (size_t)bh * (NN * DHEAD);
    const __half* Vg = g_vh + (size_t)bh * (NN * DHEAD);
    const uint32_t sK = (uint32_t)__cvta_generic_to_shared(Ks);
    const uint32_t sV = (uint32_t)__cvta_generic_to_shared(Vs);

    // persistent Q fragments, direct 4B gmem loads (Q already scaled by 0.125)
    uint32_t qf[4][4];
    {
        const int r0 = q0 + w * 16;
        #pragma unroll
        for (int kk = 0; kk < 4; kk++) {
            qf[kk][0] = *(const uint32_t*)(Qg + (size_t)(r0 + g) * 64 + kk * 16 + 2 * tg);
            qf[kk][1] = *(const uint32_t*)(Qg + (size_t)(r0 + g + 8) * 64 + kk * 16 + 2 * tg);
            qf[kk][2] = *(const uint32_t*)(Qg + (size_t)(r0 + g) * 64 + kk * 16 + 2 * tg + 8);
            qf[kk][3] = *(const uint32_t*)(Qg + (size_t)(r0 + g + 8) * 64 + kk * 16 + 2 * tg + 8);
        }
    }

    float Of[8][4];
    #pragma unroll
    for (int nt = 0; nt < 8; nt++)
        #pragma unroll
        for (int r = 0; r < 4; r++) Of[nt][r] = 0.f;
    float rs0 = 0.f, rs1 = 0.f;

    // prologue: tile 0 -> buffer 0
    for (int id = tid; id < 512; id += 256) {
        int r = id >> 3, ch = (id & 7) * 8;
        cp16(sK + (r * 72 + ch) * 2, Kg + r * 64 + ch);
        cp16(sV + (r * 72 + ch) * 2, Vg + r * 64 + ch);
    }
    CP_COMMIT();

    for (int kt = 0; kt < 16; kt++) {
        CP_WAIT0();
        __syncthreads();
        const int buf = kt & 1;
        if (kt + 1 < 16) {
            const int nb = buf ^ 1;
            const __half* Kn = Kg + (size_t)(kt + 1) * 4096;
            const __half* Vn = Vg + (size_t)(kt + 1) * 4096;
            for (int id = tid; id < 512; id += 256) {
                int r = id >> 3, ch = (id & 7) * 8;
                cp16(sK + (nb * 64 * 72 + r * 72 + ch) * 2, Kn + r * 64 + ch);
                cp16(sV + (nb * 64 * 72 + r * 72 + ch) * 2, Vn + r * 64 + ch);
            }
            CP_COMMIT();
        }
        // S = Q K^T  (16 q x 64 kv per warp)
        float sc[8][4];
        #pragma unroll
        for (int nt = 0; nt < 8; nt++) {
            sc[nt][0] = sc[nt][1] = sc[nt][2] = sc[nt][3] = 0.f;
            #pragma unroll
            for (int kk = 0; kk < 4; kk++) {
                uint32_t bb[2];
                ldsm2(bb, sK + (buf * 64 * 72 + (nt * 8 + (lane & 7)) * 72
                                 + kk * 16 + (((lane & 15) >> 3) << 3)) * 2);
                mma_f16(sc[nt], qf[kk], bb);
            }
        }
        // exp + rowsum
        #pragma unroll
        for (int nt = 0; nt < 8; nt++) {
            sc[nt][0] = __expf(sc[nt][0]); sc[nt][1] = __expf(sc[nt][1]);
            sc[nt][2] = __expf(sc[nt][2]); sc[nt][3] = __expf(sc[nt][3]);
            rs0 += sc[nt][0] + sc[nt][1];
            rs1 += sc[nt][2] + sc[nt][3];
        }
        // O += P V  (accumulator fragment layout == A fragment layout)
        #pragma unroll
        for (int kc = 0; kc < 4; kc++) {
            uint32_t pa[4];
            pa[0] = h2_as_u32(__floats2half2_rn(sc[2*kc][0],   sc[2*kc][1]));
            pa[1] = h2_as_u32(__floats2half2_rn(sc[2*kc][2],   sc[2*kc][3]));
            pa[2] = h2_as_u32(__floats2half2_rn(sc[2*kc+1][0], sc[2*kc+1][1]));
            pa[3] = h2_as_u32(__floats2half2_rn(sc[2*kc+1][2], sc[2*kc+1][3]));
            #pragma unroll
            for (int nt = 0; nt < 8; nt++) {
                uint32_t bb[2];
                ldsm2t(bb, sV + (buf * 64 * 72 + (kc * 16 + (lane & 15)) * 72 + nt * 8) * 2);
                mma_f16(Of[nt], pa, bb);
            }
        }
    }

    rs0 += __shfl_xor_sync(0xffffffffu, rs0, 1);
    rs0 += __shfl_xor_sync(0xffffffffu, rs0, 2);
    rs1 += __shfl_xor_sync(0xffffffffu, rs1, 1);
    rs1 += __shfl_xor_sync(0xffffffffu, rs1, 2);
    float inv0 = 1.f / rs0, inv1 = 1.f / rs1;

    const int n0 = q0 + w * 16 + g;
    #pragma unroll
    for (int nt = 0; nt < 8; nt++) {
        int col = h * 64 + nt * 8 + 2 * tg;
        __half2* p0 = (__half2*)(g_xattnh + ((size_t)b * NN + n0) * HID + col);
        __half2* p1 = (__half2*)(g_xattnh + ((size_t)b * NN + n0 + 8) * HID + col);
        *p0 = __floats2half2_rn(Of[nt][0] * inv0, Of[nt][1] * inv0);
        *p1 = __floats2half2_rn(Of[nt][2] * inv1, Of[nt][3] * inv1);
    }
}

// ---------------- fp16 tensor-core GEMM: C[M,N] = (A@B) * OUTSCALE ----------------
// A [M,K] half, B [K,N] half, C fp32. 128x128 tile, K-chunk 32, double-buffered.
#define TGH_SMEM ((2*128*40 + 2*32*136) * 2)   // 37888 B
__global__ void __launch_bounds__(256) tgemm_h(const __half* __restrict__ A,
                                               const __half* __restrict__ B,
                                               float* __restrict__ C,
                                               int M, int N, int K) {
    extern __shared__ __half smh[];
    __half* As = smh;                  // [2][128][40]
    __half* Bs = smh + 2 * 128 * 40;   // [2][32][136]
    const int tid = threadIdx.x;
    const int crow = blockIdx.y * 128;
    const int ccol = blockIdx.x * 128;
    const int lane = tid & 31, wid = tid >> 5;
    const int wm = wid & 1, wn = wid >> 1;
    const int g = lane >> 2, tg = lane & 3;
    const uint32_t sA = (uint32_t)__cvta_generic_to_shared(As);
    const uint32_t sB = (uint32_t)__cvta_generic_to_shared(Bs);

    float acc[4][4][4];
    #pragma unroll
    for (int i = 0; i < 4; i++)
        #pragma unroll
        for (int j = 0; j < 4; j++)
            #pragma unroll
            for (int r = 0; r < 4; r++) acc[i][j][r] = 0.f;

    // prologue
    #pragma unroll
    for (int s = 0; s < 2; s++) {
        int id = tid + s * 256;
        int r = id >> 2, ch = (id & 3) * 8;
        cp16(sA + (r * 40 + ch) * 2, A + (size_t)(crow + r) * K + ch);
        int rb = id >> 4, cb = (id & 15) * 8;
        cp16(sB + (rb * 136 + cb) * 2, B + (size_t)rb * N + ccol + cb);
    }
    CP_COMMIT();

    const int nk = K >> 5;
    for (int it = 0; it < nk; it++) {
        CP_WAIT0();
        __syncthreads();
        const int buf = it & 1;
        if (it + 1 < nk) {
            const int nb = buf ^ 1;
            const __half* Agn = A + (size_t)(it + 1) * 32;
            const __half* Bgn = B + (size_t)(it + 1) * 32 * N;
            #pragma unroll
            for (int s = 0; s < 2; s++) {
                int id = tid + s * 256;
                int r = id >> 2, ch = (id & 3) * 8;
                cp16(sA + ((nb * 128 + r) * 40 + ch) * 2, Agn + (size_t)(crow + r) * K + ch);
                int rb = id >> 4, cb = (id & 15) * 8;
                cp16(sB + ((nb * 32 + rb) * 136 + cb) * 2, Bgn + (size_t)rb * N + ccol + cb);
            }
            CP_COMMIT();
        }
        #pragma unroll
        for (int ks = 0; ks < 32; ks += 16) {
            uint32_t af[4][4];
            #pragma unroll
            for (int mt = 0; mt < 4; mt++) {
                int r = wm * 64 + mt * 16 + (lane & 15);
                int c = ks + ((lane >> 4) << 3);
                ldsm4(af[mt], sA + ((buf * 128 + r) * 40 + c) * 2);
            }
            uint32_t bf[4][2];
            #pragma unroll
            for (int nt = 0; nt < 4; nt++) {
                int r = ks + (lane & 15);
                int c = wn * 32 + nt * 8;
                ldsm2t(bf[nt], sB + ((buf * 32 + r) * 136 + c) * 2);
            }
            #pragma unroll
            for (int mt = 0; mt < 4; mt++)
                #pragma unroll
                for (int nt = 0; nt < 4; nt++)
                    mma_f16(acc[mt][nt], af[mt], bf[nt]);
        }
        __syncthreads();
    }

    #pragma unroll
    for (int mt = 0; mt < 4; mt++) {
        const int r0 = crow + wm * 64 + mt * 16 + g;
        #pragma unroll
        for (int nt = 0; nt < 4; nt++) {
            const int c0 = ccol + wn * 32 + nt * 8 + 2 * tg;
            float2* p0 = (float2*)(C + (size_t)r0 * N + c0);
            float2* p1 = (float2*)(C + (size_t)(r0 + 8) * N + c0);
            *p0 = make_float2(acc[mt][nt][0] * OUTSCALE, acc[mt][nt][1] * OUTSCALE);
            *p1 = make_float2(acc[mt][nt][2] * OUTSCALE, acc[mt][nt][3] * OUTSCALE);
        }
    }
}

// ---------------- post-attention ----------------
__global__ void __launch_bounds__(256) post_attn_kernel(const float* __restrict__ x,
                                                        const float* __restrict__ agp) {
    __shared__ float buf[HID];
    __shared__ float red[256];
    const int tid = threadIdx.x;
    const int row = blockIdx.x;
    const int b = row >> 10;
    const float* ar = g_ao + (size_t)row * HID;
    float acc = 0.f;
    for (int k = tid; k < HID; k += 256) { float v = ar[k]; buf[k] = v; acc += v * v; }
    red[tid] = acc; __syncthreads();
    for (int st = 128; st > 0; st >>= 1) { if (tid < st) red[tid] += red[tid + st]; __syncthreads(); }
    float rms = rsqrtf(red[0] * (1.f / HID) + 1e-4f);
    float eg = expf(agp[0]);
    const float* xr = x + (size_t)row * HID;
    float acc2 = 0.f;
    for (int k = tid; k < HID; k += 256) {
        float xa = buf[k] * rms * eg;
        float xm = (0.7f * xr[k] + 0.3f * xa) * MP_ADD_INV;
        g_xmid[(size_t)row * HID + k] = xm;
        buf[k] = xm;
        acc2 += xm * xm;
    }
    __syncthreads();
    red[tid] = acc2; __syncthreads();
    for (int st = 128; st > 0; st >>= 1) { if (tid < st) red[tid] += red[tid + st]; __syncthreads(); }
    float rms2 = rsqrtf(red[0] * (1.f / HID) + 1e-4f);
    const float* gs = g_cond + (size_t)b * 2 * HID;
    for (int k = tid; k < HID; k += 256)
        g_xc2h[(size_t)row * HID + k] = __float2half_rn(buf[k] * rms2 * (1.f + gs[k]) + gs[HID + k]);
}

// ---------------- MLP hidden activation ----------------
__global__ void __launch_bounds__(256) mlp_act_kernel() {
    __shared__ float buf[MLPD];
    __shared__ float red[256];
    const int tid = threadIdx.x;
    const int row = blockIdx.x;
    const float* hr = g_h + (size_t)row * MLPD;
    float acc = 0.f;
    for (int k = tid; k < MLPD; k += 256) { float v = hr[k]; buf[k] = v; acc += v * v; }
    red[tid] = acc; __syncthreads();
    for (int st = 128; st > 0; st >>= 1) { if (tid < st) red[tid] += red[tid + st]; __syncthreads(); }
    float rms = rsqrtf(red[0] * (1.f / MLPD) + 1e-4f);
    for (int k = tid; k < MLPD; k += 256) {
        float u = buf[k] * rms;
        float si = u / (1.f + expf(-u)) * INV_SILU;
        g_h2h[(size_t)row * MLPD + k] = __float2half_rn(si);
    }
}

// ---------------- final ----------------
__global__ void __launch_bounds__(256) final_kernel(const float* __restrict__ mgp,
                                                    float* __restrict__ out) {
    __shared__ float buf[HID];
    __shared__ float red[256];
    const int tid = threadIdx.x;
    const int row = blockIdx.x;
    const float* mr = g_m + (size_t)row * HID;
    float acc = 0.f;
    for (int k = tid; k < HID; k += 256) { float v = mr[k]; buf[k] = v; acc += v * v; }
    red[tid] = acc; __syncthreads();
    for (int st = 128; st > 0; st >>= 1) { if (tid < st) red[tid] += red[tid + st]; __syncthreads(); }
    float rms = rsqrtf(red[0] * (1.f / HID) + 1e-4f);
    float eg = expf(mgp[0]);
    for (int k = tid; k < HID; k += 256) {
        float xm = buf[k] * rms * eg;
        out[(size_t)row * HID + k] = (0.7f * g_xmid[(size_t)row * HID + k] + 0.3f * xm) * MP_ADD_INV;
    }
}

// ---------------- launch ----------------
extern "C" void kernel_launch(void* const* d_in, const int* in_sizes, int n_in,
                              void* d_out, int out_size) {
    (void)in_sizes; (void)n_in; (void)out_size;
    const float* x         = (const float*)d_in[0];
    const float* c         = (const float*)d_in[1];
    const float* w_cond    = (const float*)d_in[2];
    const float* w_qkv     = (const float*)d_in[3];
    const float* w_out     = (const float*)d_in[4];
    const float* w_mlp1    = (const float*)d_in[5];
    const float* w_mlp2    = (const float*)d_in[6];
    const float* attn_gain = (const float*)d_in[7];
    const float* mlp_gain  = (const float*)d_in[8];
    float* out = (float*)d_out;

    void *p_scond, *p_xc1, *p_qkv, *p_xattn, *p_ao, *p_xc2, *p_h, *p_h2, *p_m;
    void *p_wq, *p_wo, *p_wm1, *p_wm2;
    cudaGetSymbolAddress(&p_scond, g_s_cond);
    cudaGetSymbolAddress(&p_xc1,   g_xc1h);
    cudaGetSymbolAddress(&p_qkv,   g_qkv);
    cudaGetSymbolAddress(&p_xattn, g_xattnh);
    cudaGetSymbolAddress(&p_ao,    g_ao);
    cudaGetSymbolAddress(&p_xc2,   g_xc2h);
    cudaGetSymbolAddress(&p_h,     g_h);
    cudaGetSymbolAddress(&p_h2,    g_h2h);
    cudaGetSymbolAddress(&p_m,     g_m);
    cudaGetSymbolAddress(&p_wq,    g_wqh);
    cudaGetSymbolAddress(&p_wo,    g_woh);
    cudaGetSymbolAddress(&p_wm1,   g_wm1h);
    cudaGetSymbolAddress(&p_wm2,   g_wm2h);

    cudaFuncSetAttribute(attn_h_kernel, cudaFuncAttributeMaxDynamicSharedMemorySize, ATTH_SMEM);
    cudaFuncSetAttribute(tgemm_h, cudaFuncAttributeMaxDynamicSharedMemorySize, TGH_SMEM);

    // weight preprocessing (fp16, x1024)
    wconv_h<<<1024, 256>>>(w_qkv,  (__half*)p_wq,  3072, 55.42562584220407f, 32.f);
    wconv_h<<<1024, 256>>>(w_out,  (__half*)p_wo,  1024, 32.f, 32.f);
    wconv_h<<<1024, 256>>>(w_mlp1, (__half*)p_wm1, 4096, 64.f, 32.f);
    wconv_h<<<4096, 256>>>(w_mlp2, (__half*)p_wm2, 1024, 32.f, 64.f);
    rowscale_kernel<<<1024, 256>>>(w_cond, (float*)p_scond, 2048, 45.25483399593904f, 32.f);

    // conditioning
    cond_act_kernel<<<16, 256>>>(c);
    cond_gemm_part<<<dim3(8, 8), 256>>>(w_cond);
    cond_gemm_reduce<<<32, 256>>>();

    // attention branch
    xcond_kernel<<<ROWS, 256>>>(x, (__half*)p_xc1);
    tgemm_h<<<dim3(24, 32), 256, TGH_SMEM>>>((const __half*)p_xc1, (const __half*)p_wq,
                                             (float*)p_qkv, ROWS, 3 * HID, HID);
    qkv_norm_kernel<<<ROWS, 256>>>();
    attn_h_kernel<<<dim3(8, 64), 256, ATTH_SMEM>>>();
    tgemm_h<<<dim3(8, 32), 256, TGH_SMEM>>>((const __half*)p_xattn, (const __half*)p_wo,
                                            (float*)p_ao, ROWS, HID, HID);
    post_attn_kernel<<<ROWS, 256>>>(x, attn_gain);

    // MLP branch
    tgemm_h<<<dim3(32, 32), 256, TGH_SMEM>>>((const __half*)p_xc2, (const __half*)p_wm1,
                                             (float*)p_h, ROWS, MLPD, HID);
    mlp_act_kernel<<<ROWS, 256>>>();
    tgemm_h<<<dim3(8, 32), 256, TGH_SMEM>>>((const __half*)p_h2, (const __half*)p_wm2,
                                            (float*)p_m, ROWS, HID, MLPD);
    final_kernel<<<ROWS, 256>>>(mlp_gain, out);
}

// round 11
// speedup vs baseline: 5.7402x; 1.0780x over previous
#include <cuda_runtime.h>
#include <cuda_fp16.h>
#include <math.h>
#include <stdint.h>

#define BB 4
#define NN 1024
#define HID 1024
#define NHEADS 16
#define DHEAD 64
#define MLPD 4096
#define ROWS (BB*NN)   // 4096

// ---------------- scratch ----------------
__device__ float g_s_cond[HID];
__device__ float g_ccs[BB*HID];
__device__ float g_cond[BB*2*HID];
__device__ float g_condp[8][4*2048];
__device__ __half g_xc1h[ROWS*HID];
__device__ __half g_qkvh[ROWS*3*HID];
__device__ __half g_qh[ROWS*HID];
__device__ __half g_kh[ROWS*HID];
__device__ __half g_vh[ROWS*HID];
__device__ __half g_xattnh[ROWS*HID];
__device__ __half g_aoh[ROWS*HID];
__device__ float g_xmid[ROWS*HID];
__device__ __half g_xc2h[ROWS*HID];
__device__ __half g_hh[ROWS*MLPD];
__device__ __half g_h2h[ROWS*MLPD];
__device__ __half g_mh[ROWS*HID];
// fp16 pre-scaled weights (x1024; GEMM epilogue multiplies by 1/1024)
__device__ __half g_wqh[HID*3*HID];
__device__ __half g_woh[HID*HID];
__device__ __half g_wm1h[HID*MLPD];
__device__ __half g_wm2h[MLPD*HID];

#define MP_ADD_INV 1.3130643285972254f
#define INV_SILU 1.6778523489932886f
#define OUTSCALE 0.0009765625f   // 1/1024

__device__ __forceinline__ uint32_t h2_as_u32(__half2 v) {
    union { __half2 h; uint32_t u; } cvt;
    cvt.h = v;
    return cvt.u;
}
__device__ __forceinline__ float wredsum(float v) {
    v += __shfl_xor_sync(0xffffffffu, v, 16);
    v += __shfl_xor_sync(0xffffffffu, v, 8);
    v += __shfl_xor_sync(0xffffffffu, v, 4);
    v += __shfl_xor_sync(0xffffffffu, v, 2);
    v += __shfl_xor_sync(0xffffffffu, v, 1);
    return v;
}

__device__ __forceinline__ void cp16(uint32_t dst, const void* src) {
    asm volatile("cp.async.cg.shared.global [%0], [%1], 16;" :: "r"(dst), "l"(src));
}
#define CP_COMMIT() asm volatile("cp.async.commit_group;")
#define CP_WAIT0()  asm volatile("cp.async.wait_group 0;")
#define CP_WAIT1()  asm volatile("cp.async.wait_group 1;")

__device__ __forceinline__ void mma_f16(float* c, const uint32_t* a, const uint32_t* b) {
    asm volatile("mma.sync.aligned.m16n8k16.row.col.f32.f16.f16.f32 "
        "{%0,%1,%2,%3}, {%4,%5,%6,%7}, {%8,%9}, {%0,%1,%2,%3};"
        : "+f"(c[0]), "+f"(c[1]), "+f"(c[2]), "+f"(c[3])
        : "r"(a[0]), "r"(a[1]), "r"(a[2]), "r"(a[3]), "r"(b[0]), "r"(b[1]));
}
__device__ __forceinline__ void ldsm4(uint32_t* r, uint32_t addr) {
    asm volatile("ldmatrix.sync.aligned.m8n8.x4.shared.b16 {%0,%1,%2,%3}, [%4];"
        : "=r"(r[0]), "=r"(r[1]), "=r"(r[2]), "=r"(r[3]) : "r"(addr));
}
__device__ __forceinline__ void ldsm2(uint32_t* r, uint32_t addr) {
    asm volatile("ldmatrix.sync.aligned.m8n8.x2.shared.b16 {%0,%1}, [%2];"
        : "=r"(r[0]), "=r"(r[1]) : "r"(addr));
}
__device__ __forceinline__ void ldsm2t(uint32_t* r, uint32_t addr) {
    asm volatile("ldmatrix.sync.aligned.m8n8.x2.trans.shared.b16 {%0,%1}, [%2];"
        : "=r"(r[0]), "=r"(r[1]) : "r"(addr));
}

// ---------------- weight convert: row-normalize + scale*1024 -> fp16 ----------------
__global__ void __launch_bounds__(256) wconv_h(const float* __restrict__ w,
                                               __half* __restrict__ wt,
                                               int cols, float alpha, float sqin) {
    __shared__ float red[8];
    const int tid = threadIdx.x;
    const int lane = tid & 31, wrp = tid >> 5;
    const int row = blockIdx.x;
    const float* wr = w + (size_t)row * cols;
    const int c4 = cols >> 2;
    float acc = 0.f;
    for (int j = tid; j < c4; j += 256) {
        float4 v = ((const float4*)wr)[j];
        acc += v.x * v.x + v.y * v.y + v.z * v.z + v.w * v.w;
    }
    acc = wredsum(acc);
    if (lane == 0) red[wrp] = acc;
    __syncthreads();
    float tot = red[0] + red[1] + red[2] + red[3] + red[4] + red[5] + red[6] + red[7];
    float s = 1024.f / ((sqrtf(tot) * alpha + 1e-4f) * sqin);
    __half* wo = wt + (size_t)row * cols;
    for (int j = tid; j < c4; j += 256) {
        float4 v = ((const float4*)wr)[j];
        *(__half2*)(wo + 4 * j)     = __floats2half2_rn(v.x * s, v.y * s);
        *(__half2*)(wo + 4 * j + 2) = __floats2half2_rn(v.z * s, v.w * s);
    }
}

__global__ void __launch_bounds__(256) rowscale_kernel(const float* __restrict__ w,
                                                       float* __restrict__ s,
                                                       int cols, float alpha, float sqin) {
    __shared__ float red[8];
    const int tid = threadIdx.x;
    const int lane = tid & 31, wrp = tid >> 5;
    const int row = blockIdx.x;
    const float* wr = w + (size_t)row * cols;
    const int c4 = cols >> 2;
    float acc = 0.f;
    for (int j = tid; j < c4; j += 256) {
        float4 v = ((const float4*)wr)[j];
        acc += v.x * v.x + v.y * v.y + v.z * v.z + v.w * v.w;
    }
    acc = wredsum(acc);
    if (lane == 0) red[wrp] = acc;
    __syncthreads();
    if (tid == 0) {
        float tot = red[0] + red[1] + red[2] + red[3] + red[4] + red[5] + red[6] + red[7];
        s[row] = 1.f / ((sqrtf(tot) * alpha + 1e-4f) * sqin);
    }
}

// ---------------- conditioning (fp32 path) ----------------
__global__ void __launch_bounds__(256) cond_act_kernel(const float* __restrict__ c) {
    int idx = blockIdx.x * 256 + threadIdx.x;
    float v = c[idx];
    float si = v / (1.f + expf(-v)) * INV_SILU;
    g_ccs[idx] = si * g_s_cond[idx & (HID - 1)];
}

__global__ void __launch_bounds__(256) cond_gemm_part(const float* __restrict__ w) {
    __shared__ float cs[4 * 128];
    const int tid = threadIdx.x;
    const int jb = blockIdx.x, ks = blockIdx.y;
    const int k0 = ks * 128;
    for (int t = tid; t < 512; t += 256) {
        int bidx = t >> 7, kk = t & 127;
        cs[t] = g_ccs[bidx * HID + k0 + kk];
    }
    __syncthreads();
    int j = jb * 256 + tid;
    float a0 = 0.f, a1 = 0.f, a2 = 0.f, a3 = 0.f;
    for (int kk = 0; kk < 128; kk++) {
        float wv = w[(size_t)(k0 + kk) * (2 * HID) + j];
        a0 = fmaf(cs[kk], wv, a0);
        a1 = fmaf(cs[128 + kk], wv, a1);
        a2 = fmaf(cs[256 + kk], wv, a2);
        a3 = fmaf(cs[384 + kk], wv, a3);
    }
    g_condp[ks][0 * 2048 + j] = a0;
    g_condp[ks][1 * 2048 + j] = a1;
    g_condp[ks][2 * 2048 + j] = a2;
    g_condp[ks][3 * 2048 + j] = a3;
}

__global__ void __launch_bounds__(256) cond_gemm_reduce() {
    int i = blockIdx.x * 256 + threadIdx.x;
    float s = 0.f;
    #pragma unroll
    for (int ks = 0; ks < 8; ks++) s += g_condp[ks][i];
    g_cond[i] = s;
}

// ---------------- xcond -> fp16 (4 elems/thread, 1 barrier) ----------------
__global__ void __launch_bounds__(256) xcond_kernel(const float* __restrict__ x,
                                                    __half* __restrict__ out) {
    __shared__ float red[8];
    const int tid = threadIdx.x;
    const int lane = tid & 31, wrp = tid >> 5;
    const int row = blockIdx.x;
    const int b = row >> 10;
    const float* xr = x + (size_t)row * HID;
    float4 v = ((const float4*)xr)[tid];
    float acc = v.x * v.x + v.y * v.y + v.z * v.z + v.w * v.w;
    acc = wredsum(acc);
    if (lane == 0) red[wrp] = acc;
    __syncthreads();
    float tot = red[0] + red[1] + red[2] + red[3] + red[4] + red[5] + red[6] + red[7];
    float rms = rsqrtf(tot * (1.f / HID) + 1e-4f);
    const float* gs = g_cond + (size_t)b * 2 * HID;
    const int k0 = 4 * tid;
    float o0 = v.x * rms * (1.f + gs[k0])     + gs[HID + k0];
    float o1 = v.y * rms * (1.f + gs[k0 + 1]) + gs[HID + k0 + 1];
    float o2 = v.z * rms * (1.f + gs[k0 + 2]) + gs[HID + k0 + 2];
    float o3 = v.w * rms * (1.f + gs[k0 + 3]) + gs[HID + k0 + 3];
    __half* orow = out + (size_t)row * HID + k0;
    *(__half2*)orow       = __floats2half2_rn(o0, o1);
    *(__half2*)(orow + 2) = __floats2half2_rn(o2, o3);
}

// ---------------- qkv normalize + head split -> fp16 (1 barrier) ----------------
// Head h's 64 elements == pairs [32h, 32h+32) == exactly the 32 lanes of warp h (mod 8).
__global__ void __launch_bounds__(256) qkv_norm_kernel() {
    __shared__ float red[24];
    __shared__ float sqr[16], skr[16];
    const int tid = threadIdx.x;
    const int lane = tid & 31, wrp = tid >> 5;
    const int row = blockIdx.x;
    const __half2* qr2 = (const __half2*)(g_qkvh + (size_t)row * 3 * HID);
    float2 a0 = __half22float2(qr2[tid]);
    float2 a1 = __half22float2(qr2[tid + 256]);
    float2 b0 = __half22float2(qr2[512 + tid]);
    float2 b1 = __half22float2(qr2[512 + tid + 256]);
    float2 c0 = __half22float2(qr2[1024 + tid]);
    float2 c1 = __half22float2(qr2[1024 + tid + 256]);
    float qh0 = a0.x * a0.x + a0.y * a0.y;
    float qh1 = a1.x * a1.x + a1.y * a1.y;
    float kh0 = b0.x * b0.x + b0.y * b0.y;
    float kh1 = b1.x * b1.x + b1.y * b1.y;
    float av  = c0.x * c0.x + c0.y * c0.y + c1.x * c1.x + c1.y * c1.y;
    float aq = qh0 + qh1, ak = kh0 + kh1;
    aq = wredsum(aq); ak = wredsum(ak); av = wredsum(av);
    qh0 = wredsum(qh0); qh1 = wredsum(qh1);
    kh0 = wredsum(kh0); kh1 = wredsum(kh1);
    if (lane == 0) {
        red[wrp] = aq; red[8 + wrp] = ak; red[16 + wrp] = av;
        sqr[wrp] = qh0; sqr[8 + wrp] = qh1;
        skr[wrp] = kh0; skr[8 + wrp] = kh1;
    }
    __syncthreads();
    float gq = 0.f, gk = 0.f, gv = 0.f;
    #pragma unroll
    for (int i = 0; i < 8; i++) { gq += red[i]; gk += red[8 + i]; gv += red[16 + i]; }
    float rq = rsqrtf(gq * (1.f / HID) + 1e-4f);
    float rk = rsqrtf(gk * (1.f / HID) + 1e-4f);
    float rv = rsqrtf(gv * (1.f / HID) + 1e-4f);
    const int h0 = wrp, h1 = wrp + 8;
    float scq0 = rq * rsqrtf(rq * rq * sqr[h0] + 1e-6f) * 0.125f;
    float scq1 = rq * rsqrtf(rq * rq * sqr[h1] + 1e-6f) * 0.125f;
    float sck0 = rk * rsqrtf(rk * rk * skr[h0] + 1e-6f);
    float sck1 = rk * rsqrtf(rk * rk * skr[h1] + 1e-6f);
    const int b = row >> 10, n = row & (NN - 1);
    size_t o0 = ((size_t)(b * NHEADS + h0) * NN + n) * DHEAD + 2 * lane;
    size_t o1 = ((size_t)(b * NHEADS + h1) * NN + n) * DHEAD + 2 * lane;
    *(__half2*)(g_qh + o0) = __floats2half2_rn(a0.x * scq0, a0.y * scq0);
    *(__half2*)(g_qh + o1) = __floats2half2_rn(a1.x * scq1, a1.y * scq1);
    *(__half2*)(g_kh + o0) = __floats2half2_rn(b0.x * sck0, b0.y * sck0);
    *(__half2*)(g_kh + o1) = __floats2half2_rn(b1.x * sck1, b1.y * sck1);
    *(__half2*)(g_vh + o0) = __floats2half2_rn(c0.x * rv, c0.y * rv);
    *(__half2*)(g_vh + o1) = __floats2half2_rn(c1.x * rv, c1.y * rv);
}

// ---------------- fp16 flash attention (no max track; P stays in registers) ----------------
#define ATTH_SMEM (2*(64*72 + 64*72)*2)
__global__ void __launch_bounds__(256) attn_h_kernel() {
    extern __shared__ __half smh[];
    __half* Ks = smh;                 // [2][64][72]
    __half* Vs = smh + 2 * 64 * 72;   // [2][64][72]
    const int tid = threadIdx.x;
    const int lane = tid & 31, w = tid >> 5;
    const int g = lane >> 2, tg = lane & 3;
    const int bh = blockIdx.y, q0 = blockIdx.x * 128;
    const int b = bh >> 4, h = bh & 15;
    const __half* Qg = g_qh + (size_t)bh * (NN * DHEAD);
    const __half* Kg = g_kh + (size_t)bh * (NN * DHEAD);
    const __half* Vg = g_vh + (size_t)bh * (NN * DHEAD);
    const uint32_t sK = (uint32_t)__cvta_generic_to_shared(Ks);
    const uint32_t sV = (uint32_t)__cvta_generic_to_shared(Vs);

    uint32_t qf[4][4];
    {
        const int r0 = q0 + w * 16;
        #pragma unroll
        for (int kk = 0; kk < 4; kk++) {
            qf[kk][0] = *(const uint32_t*)(Qg + (size_t)(r0 + g) * 64 + kk * 16 + 2 * tg);
            qf[kk][1] = *(const uint32_t*)(Qg + (size_t)(r0 + g + 8) * 64 + kk * 16 + 2 * tg);
            qf[kk][2] = *(const uint32_t*)(Qg + (size_t)(r0 + g) * 64 + kk * 16 + 2 * tg + 8);
            qf[kk][3] = *(const uint32_t*)(Qg + (size_t)(r0 + g + 8) * 64 + kk * 16 + 2 * tg + 8);
        }
    }

    float Of[8][4];
    #pragma unroll
    for (int nt = 0; nt < 8; nt++)
        #pragma unroll
        for (int r = 0; r < 4; r++) Of[nt][r] = 0.f;
    float rs0 = 0.f, rs1 = 0.f;

    for (int id = tid; id < 512; id += 256) {
        int r = id >> 3, ch = (id & 7) * 8;
        cp16(sK + (r * 72 + ch) * 2, Kg + r * 64 + ch);
        cp16(sV + (r * 72 + ch) * 2, Vg + r * 64 + ch);
    }
    CP_COMMIT();

    for (int kt = 0; kt < 16; kt++) {
        CP_WAIT0();
        __syncthreads();
        const int buf = kt & 1;
        if (kt + 1 < 16) {
            const int nb = buf ^ 1;
            const __half* Kn = Kg + (size_t)(kt + 1) * 4096;
            const __half* Vn = Vg + (size_t)(kt + 1) * 4096;
            for (int id = tid; id < 512; id += 256) {
                int r = id >> 3, ch = (id & 7) * 8;
                cp16(sK + (nb * 64 * 72 + r * 72 + ch) * 2, Kn + r * 64 + ch);
                cp16(sV + (nb * 64 * 72 + r * 72 + ch) * 2, Vn + r * 64 + ch);
            }
            CP_COMMIT();
        }
        float sc[8][4];
        #pragma unroll
        for (int nt = 0; nt < 8; nt++) {
            sc[nt][0] = sc[nt][1] = sc[nt][2] = sc[nt][3] = 0.f;
            #pragma unroll
            for (int kk = 0; kk < 4; kk++) {
                uint32_t bb[2];
                ldsm2(bb, sK + (buf * 64 * 72 + (nt * 8 + (lane & 7)) * 72
                                 + kk * 16 + (((lane & 15) >> 3) << 3)) * 2);
                mma_f16(sc[nt], qf[kk], bb);
            }
        }
        #pragma unroll
        for (int nt = 0; nt < 8; nt++) {
            sc[nt][0] = __expf(sc[nt][0]); sc[nt][1] = __expf(sc[nt][1]);
            sc[nt][2] = __expf(sc[nt][2]); sc[nt][3] = __expf(sc[nt][3]);
            rs0 += sc[nt][0] + sc[nt][1];
            rs1 += sc[nt][2] + sc[nt][3];
        }
        #pragma unroll
        for (int kc = 0; kc < 4; kc++) {
            uint32_t pa[4];
            pa[0] = h2_as_u32(__floats2half2_rn(sc[2*kc][0],   sc[2*kc][1]));
            pa[1] = h2_as_u32(__floats2half2_rn(sc[2*kc][2],   sc[2*kc][3]));
            pa[2] = h2_as_u32(__floats2half2_rn(sc[2*kc+1][0], sc[2*kc+1][1]));
            pa[3] = h2_as_u32(__floats2half2_rn(sc[2*kc+1][2], sc[2*kc+1][3]));
            #pragma unroll
            for (int nt = 0; nt < 8; nt++) {
                uint32_t bb[2];
                ldsm2t(bb, sV + (buf * 64 * 72 + (kc * 16 + (lane & 15)) * 72 + nt * 8) * 2);
                mma_f16(Of[nt], pa, bb);
            }
        }
    }

    rs0 += __shfl_xor_sync(0xffffffffu, rs0, 1);
    rs0 += __shfl_xor_sync(0xffffffffu, rs0, 2);
    rs1 += __shfl_xor_sync(0xffffffffu, rs1, 1);
    rs1 += __shfl_xor_sync(0xffffffffu, rs1, 2);
    float inv0 = 1.f / rs0, inv1 = 1.f / rs1;

    const int n0 = q0 + w * 16 + g;
    #pragma unroll
    for (int nt = 0; nt < 8; nt++) {
        int col = h * 64 + nt * 8 + 2 * tg;
        __half2* p0 = (__half2*)(g_xattnh + ((size_t)b * NN + n0) * HID + col);
        __half2* p1 = (__half2*)(g_xattnh + ((size_t)b * NN + n0 + 8) * HID + col);
        *p0 = __floats2half2_rn(Of[nt][0] * inv0, Of[nt][1] * inv0);
        *p1 = __floats2half2_rn(Of[nt][2] * inv1, Of[nt][3] * inv1);
    }
}

// ---------------- fp16 GEMM, 3-stage pipeline, half output: C = (A@B)*OUTSCALE ----------------
#define TGH_SMEM (3*(128*40 + 32*136) * 2)   // 56832 B
__device__ __forceinline__ void tg_load(const __half* A, const __half* B,
                                        uint32_t sA, uint32_t sB,
                                        int st, int kt, int tid,
                                        int crow, int ccol, int K, int N) {
    const __half* Ags = A + (size_t)kt * 32;
    const __half* Bgs = B + (size_t)kt * 32 * N;
    #pragma unroll
    for (int s = 0; s < 2; s++) {
        int id = tid + s * 256;
        int r = id >> 2, ch = (id & 3) * 8;
        cp16(sA + ((st * 128 + r) * 40 + ch) * 2, Ags + (size_t)(crow + r) * K + ch);
        int rb = id >> 4, cb = (id & 15) * 8;
        cp16(sB + ((st * 32 + rb) * 136 + cb) * 2, Bgs + (size_t)rb * N + ccol + cb);
    }
    CP_COMMIT();
}

__global__ void __launch_bounds__(256) tgemm_h(const __half* __restrict__ A,
                                               const __half* __restrict__ B,
                                               __half* __restrict__ C,
                                               int M, int N, int K) {
    extern __shared__ __half smh[];
    __half* As = smh;                  // [3][128][40]
    __half* Bs = smh + 3 * 128 * 40;   // [3][32][136]
    const int tid = threadIdx.x;
    const int crow = blockIdx.y * 128;
    const int ccol = blockIdx.x * 128;
    const int lane = tid & 31, wid = tid >> 5;
    const int wm = wid & 1, wn = wid >> 1;
    const int g = lane >> 2, tg = lane & 3;
    const uint32_t sA = (uint32_t)__cvta_generic_to_shared(As);
    const uint32_t sB = (uint32_t)__cvta_generic_to_shared(Bs);

    float acc[4][4][4];
    #pragma unroll
    for (int i = 0; i < 4; i++)
        #pragma unroll
        for (int j = 0; j < 4; j++)
            #pragma unroll
            for (int r = 0; r < 4; r++) acc[i][j][r] = 0.f;

    tg_load(A, B, sA, sB, 0, 0, tid, crow, ccol, K, N);
    tg_load(A, B, sA, sB, 1, 1, tid, crow, ccol, K, N);

    const int nk = K >> 5;
    int st = 0;
    for (int it = 0; it < nk; it++) {
        if (it + 1 < nk) { CP_WAIT1(); } else { CP_WAIT0(); }
        __syncthreads();
        if (it + 2 < nk) {
            int ns = st + 2; if (ns >= 3) ns -= 3;
            tg_load(A, B, sA, sB, ns, it + 2, tid, crow, ccol, K, N);
        }
        #pragma unroll
        for (int ks = 0; ks < 32; ks += 16) {
            uint32_t af[4][4];
            #pragma unroll
            for (int mt = 0; mt < 4; mt++) {
                int r = wm * 64 + mt * 16 + (lane & 15);
                int c = ks + ((lane >> 4) << 3);
                ldsm4(af[mt], sA + ((st * 128 + r) * 40 + c) * 2);
            }
            uint32_t bf[4][2];
            #pragma unroll
            for (int nt = 0; nt < 4; nt++) {
                int r = ks + (lane & 15);
                int c = wn * 32 + nt * 8;
                ldsm2t(bf[nt], sB + ((st * 32 + r) * 136 + c) * 2);
            }
            #pragma unroll
            for (int mt = 0; mt < 4; mt++)
                #pragma unroll
                for (int nt = 0; nt < 4; nt++)
                    mma_f16(acc[mt][nt], af[mt], bf[nt]);
        }
        __syncthreads();
        if (++st == 3) st = 0;
    }

    #pragma unroll
    for (int mt = 0; mt < 4; mt++) {
        const int r0 = crow + wm * 64 + mt * 16 + g;
        #pragma unroll
        for (int nt = 0; nt < 4; nt++) {
            const int c0 = ccol + wn * 32 + nt * 8 + 2 * tg;
            *(__half2*)(C + (size_t)r0 * N + c0) =
                __floats2half2_rn(acc[mt][nt][0] * OUTSCALE, acc[mt][nt][1] * OUTSCALE);
            *(__half2*)(C + (size_t)(r0 + 8) * N + c0) =
                __floats2half2_rn(acc[mt][nt][2] * OUTSCALE, acc[mt][nt][3] * OUTSCALE);
        }
    }
}

// ---------------- post-attention (4 elems/thread, 2 barriers) ----------------
__global__ void __launch_bounds__(256) post_attn_kernel(const float* __restrict__ x,
                                                        const float* __restrict__ agp) {
    __shared__ float red[16];
    const int tid = threadIdx.x;
    const int lane = tid & 31, wrp = tid >> 5;
    const int row = blockIdx.x;
    const int b = row >> 10;
    const __half2* ar2 = (const __half2*)(g_aoh + (size_t)row * HID);
    float2 a0 = __half22float2(ar2[2 * tid]);
    float2 a1 = __half22float2(ar2[2 * tid + 1]);
    float acc = a0.x * a0.x + a0.y * a0.y + a1.x * a1.x + a1.y * a1.y;
    acc = wredsum(acc);
    if (lane == 0) red[wrp] = acc;
    __syncthreads();
    float tot = red[0] + red[1] + red[2] + red[3] + red[4] + red[5] + red[6] + red[7];
    float rms = rsqrtf(tot * (1.f / HID) + 1e-4f);
    float eg = expf(agp[0]) * rms;
    const float* xr = x + (size_t)row * HID;
    float4 xv = ((const float4*)xr)[tid];
    float xm0 = (0.7f * xv.x + 0.3f * a0.x * eg) * MP_ADD_INV;
    float xm1 = (0.7f * xv.y + 0.3f * a0.y * eg) * MP_ADD_INV;
    float xm2 = (0.7f * xv.z + 0.3f * a1.x * eg) * MP_ADD_INV;
    float xm3 = (0.7f * xv.w + 0.3f * a1.y * eg) * MP_ADD_INV;
    ((float4*)(g_xmid + (size_t)row * HID))[tid] = make_float4(xm0, xm1, xm2, xm3);
    float acc2 = xm0 * xm0 + xm1 * xm1 + xm2 * xm2 + xm3 * xm3;
    acc2 = wredsum(acc2);
    if (lane == 0) red[8 + wrp] = acc2;
    __syncthreads();
    float tot2 = red[8] + red[9] + red[10] + red[11] + red[12] + red[13] + red[14] + red[15];
    float rms2 = rsqrtf(tot2 * (1.f / HID) + 1e-4f);
    const float* gs = g_cond + (size_t)b * 2 * HID;
    const int k0 = 4 * tid;
    float o0 = xm0 * rms2 * (1.f + gs[k0])     + gs[HID + k0];
    float o1 = xm1 * rms2 * (1.f + gs[k0 + 1]) + gs[HID + k0 + 1];
    float o2 = xm2 * rms2 * (1.f + gs[k0 + 2]) + gs[HID + k0 + 2];
    float o3 = xm3 * rms2 * (1.f + gs[k0 + 3]) + gs[HID + k0 + 3];
    __half* orow = g_xc2h + (size_t)row * HID + k0;
    *(__half2*)orow       = __floats2half2_rn(o0, o1);
    *(__half2*)(orow + 2) = __floats2half2_rn(o2, o3);
}

// ---------------- MLP hidden activation (16 elems/thread, 1 barrier) ----------------
__global__ void __launch_bounds__(256) mlp_act_kernel() {
    __shared__ float red[8];
    const int tid = threadIdx.x;
    const int lane = tid & 31, wrp = tid >> 5;
    const int row = blockIdx.x;
    const __half2* hr2 = (const __half2*)(g_hh + (size_t)row * MLPD);  // 2048 pairs
    float2 v[8];
    float acc = 0.f;
    #pragma unroll
    for (int i = 0; i < 8; i++) {
        v[i] = __half22float2(hr2[tid + 256 * i]);
        acc += v[i].x * v[i].x + v[i].y * v[i].y;
    }
    acc = wredsum(acc);
    if (lane == 0) red[wrp] = acc;
    __syncthreads();
    float tot = red[0] + red[1] + red[2] + red[3] + red[4] + red[5] + red[6] + red[7];
    float rms = rsqrtf(tot * (1.f / MLPD) + 1e-4f);
    __half2* o2 = (__half2*)(g_h2h + (size_t)row * MLPD);
    #pragma unroll
    for (int i = 0; i < 8; i++) {
        float u0 = v[i].x * rms, u1 = v[i].y * rms;
        float s0 = u0 / (1.f + __expf(-u0)) * INV_SILU;
        float s1 = u1 / (1.f + __expf(-u1)) * INV_SILU;
        o2[tid + 256 * i] = __floats2half2_rn(s0, s1);
    }
}

// ---------------- final (4 elems/thread, 1 barrier) ----------------
__global__ void __launch_bounds__(256) final_kernel(const float* __restrict__ mgp,
                                                    float* __restrict__ out) {
    __shared__ float red[8];
    const int tid = threadIdx.x;
    const int lane = tid & 31, wrp = tid >> 5;
    const int row = blockIdx.x;
    const __half2* mr2 = (const __half2*)(g_mh + (size_t)row * HID);
    float2 m0 = __half22float2(mr2[2 * tid]);
    float2 m1 = __half22float2(mr2[2 * tid + 1]);
    float acc = m0.x * m0.x + m0.y * m0.y + m1.x * m1.x + m1.y * m1.y;
    acc = wredsum(acc);
    if (lane == 0) red[wrp] = acc;
    __syncthreads();
    float tot = red[0] + red[1] + red[2] + red[3] + red[4] + red[5] + red[6] + red[7];
    float rms = rsqrtf(tot * (1.f / HID) + 1e-4f);
    float eg = expf(mgp[0]) * rms;
    float4 xm = ((const float4*)(g_xmid + (size_t)row * HID))[tid];
    float4 o;
    o.x = (0.7f * xm.x + 0.3f * m0.x * eg) * MP_ADD_INV;
    o.y = (0.7f * xm.y + 0.3f * m0.y * eg) * MP_ADD_INV;
    o.z = (0.7f * xm.z + 0.3f * m1.x * eg) * MP_ADD_INV;
    o.w = (0.7f * xm.w + 0.3f * m1.y * eg) * MP_ADD_INV;
    ((float4*)(out + (size_t)row * HID))[tid] = o;
}

// ---------------- launch ----------------
extern "C" void kernel_launch(void* const* d_in, const int* in_sizes, int n_in,
                              void* d_out, int out_size) {
    (void)in_sizes; (void)n_in; (void)out_size;
    const float* x         = (const float*)d_in[0];
    const float* c         = (const float*)d_in[1];
    const float* w_cond    = (const float*)d_in[2];
    const float* w_qkv     = (const float*)d_in[3];
    const float* w_out     = (const float*)d_in[4];
    const float* w_mlp1    = (const float*)d_in[5];
    const float* w_mlp2    = (const float*)d_in[6];
    const float* attn_gain = (const float*)d_in[7];
    const float* mlp_gain  = (const float*)d_in[8];
    float* out = (float*)d_out;

    void *p_scond, *p_xc1, *p_qkv, *p_xattn, *p_ao, *p_xc2, *p_h, *p_h2, *p_m;
    void *p_wq, *p_wo, *p_wm1, *p_wm2;
    cudaGetSymbolAddress(&p_scond, g_s_cond);
    cudaGetSymbolAddress(&p_xc1,   g_xc1h);
    cudaGetSymbolAddress(&p_qkv,   g_qkvh);
    cudaGetSymbolAddress(&p_xattn, g_xattnh);
    cudaGetSymbolAddress(&p_ao,    g_aoh);
    cudaGetSymbolAddress(&p_xc2,   g_xc2h);
    cudaGetSymbolAddress(&p_h,     g_hh);
    cudaGetSymbolAddress(&p_h2,    g_h2h);
    cudaGetSymbolAddress(&p_m,     g_mh);
    cudaGetSymbolAddress(&p_wq,    g_wqh);
    cudaGetSymbolAddress(&p_wo,    g_woh);
    cudaGetSymbolAddress(&p_wm1,   g_wm1h);
    cudaGetSymbolAddress(&p_wm2,   g_wm2h);

    cudaFuncSetAttribute(attn_h_kernel, cudaFuncAttributeMaxDynamicSharedMemorySize, ATTH_SMEM);
    cudaFuncSetAttribute(tgemm_h, cudaFuncAttributeMaxDynamicSharedMemorySize, TGH_SMEM);

    // weight preprocessing (fp16, x1024)
    wconv_h<<<1024, 256>>>(w_qkv,  (__half*)p_wq,  3072, 55.42562584220407f, 32.f);
    wconv_h<<<1024, 256>>>(w_out,  (__half*)p_wo,  1024, 32.f, 32.f);
    wconv_h<<<1024, 256>>>(w_mlp1, (__half*)p_wm1, 4096, 64.f, 32.f);
    wconv_h<<<4096, 256>>>(w_mlp2, (__half*)p_wm2, 1024, 32.f, 64.f);
    rowscale_kernel<<<1024, 256>>>(w_cond, (float*)p_scond, 2048, 45.25483399593904f, 32.f);

    // conditioning
    cond_act_kernel<<<16, 256>>>(c);
    cond_gemm_part<<<dim3(8, 8), 256>>>(w_cond);
    cond_gemm_reduce<<<32, 256>>>();

    // attention branch
    xcond_kernel<<<ROWS, 256>>>(x, (__half*)p_xc1);
    tgemm_h<<<dim3(24, 32), 256, TGH_SMEM>>>((const __half*)p_xc1, (const __half*)p_wq,
                                             (__half*)p_qkv, ROWS, 3 * HID, HID);
    qkv_norm_kernel<<<ROWS, 256>>>();
    attn_h_kernel<<<dim3(8, 64), 256, ATTH_SMEM>>>();
    tgemm_h<<<dim3(8, 32), 256, TGH_SMEM>>>((const __half*)p_xattn, (const __half*)p_wo,
                                            (__half*)p_ao, ROWS, HID, HID);
    post_attn_kernel<<<ROWS, 256>>>(x, attn_gain);

    // MLP branch
    tgemm_h<<<dim3(32, 32), 256, TGH_SMEM>>>((const __half*)p_xc2, (const __half*)p_wm1,
                                             (__half*)p_h, ROWS, MLPD, HID);
    mlp_act_kernel<<<ROWS, 256>>>();
    tgemm_h<<<dim3(8, 32), 256, TGH_SMEM>>>((const __half*)p_h2, (const __half*)p_wm2,
                                            (__half*)p_m, ROWS, HID, MLPD);
    final_kernel<<<ROWS, 256>>>(mlp_gain, out);
}

// round 17
// speedup vs baseline: 6.0676x; 1.0570x over previous
#include <cuda_runtime.h>
#include <cuda_fp16.h>
#include <math.h>
#include <stdint.h>

#define BB 4
#define NN 1024
#define HID 1024
#define NHEADS 16
#define DHEAD 64
#define MLPD 4096
#define ROWS (BB*NN)   // 4096

// ---------------- scratch ----------------
__device__ float g_s_cond[HID];
__device__ float g_ccs[BB*HID];
__device__ float g_cond[BB*2*HID];
__device__ float g_condp[8][4*2048];
__device__ __half g_xc1h[ROWS*HID];
__device__ __half g_qkvh[ROWS*3*HID];
__device__ __half g_qh[ROWS*HID];
__device__ __half g_kh[ROWS*HID];
__device__ __half g_vh[ROWS*HID];
__device__ __half g_xattnh[ROWS*HID];
__device__ __half g_aoh[ROWS*HID];
__device__ float g_xmid[ROWS*HID];
__device__ __half g_xc2h[ROWS*HID];
__device__ __half g_hh[ROWS*MLPD];
__device__ __half g_h2h[ROWS*MLPD];
__device__ __half g_mh[ROWS*HID];
// fp16 pre-scaled weights (x1024; GEMM epilogue multiplies by 1/1024)
__device__ __half g_wqh[HID*3*HID];
__device__ __half g_woh[HID*HID];
__device__ __half g_wm1h[HID*MLPD];
__device__ __half g_wm2h[MLPD*HID];

#define MP_ADD_INV 1.3130643285972254f
#define INV_SILU 1.6778523489932886f
#define OUTSCALE 0.0009765625f   // 1/1024

__device__ __forceinline__ uint32_t h2_as_u32(__half2 v) {
    union { __half2 h; uint32_t u; } cvt;
    cvt.h = v;
    return cvt.u;
}
__device__ __forceinline__ float wredsum(float v) {
    v += __shfl_xor_sync(0xffffffffu, v, 16);
    v += __shfl_xor_sync(0xffffffffu, v, 8);
    v += __shfl_xor_sync(0xffffffffu, v, 4);
    v += __shfl_xor_sync(0xffffffffu, v, 2);
    v += __shfl_xor_sync(0xffffffffu, v, 1);
    return v;
}
__device__ __forceinline__ void cp16(uint32_t dst, const void* src) {
    asm volatile("cp.async.cg.shared.global [%0], [%1], 16;" :: "r"(dst), "l"(src));
}
#define CP_COMMIT() asm volatile("cp.async.commit_group;")
#define CP_WAIT0()  asm volatile("cp.async.wait_group 0;")
#define CP_WAIT1()  asm volatile("cp.async.wait_group 1;")

__device__ __forceinline__ void mma_f16(float* c, const uint32_t* a, const uint32_t* b) {
    asm volatile("mma.sync.aligned.m16n8k16.row.col.f32.f16.f16.f32 "
        "{%0,%1,%2,%3}, {%4,%5,%6,%7}, {%8,%9}, {%0,%1,%2,%3};"
        : "+f"(c[0]), "+f"(c[1]), "+f"(c[2]), "+f"(c[3])
        : "r"(a[0]), "r"(a[1]), "r"(a[2]), "r"(a[3]), "r"(b[0]), "r"(b[1]));
}
__device__ __forceinline__ void ldsm4(uint32_t* r, uint32_t addr) {
    asm volatile("ldmatrix.sync.aligned.m8n8.x4.shared.b16 {%0,%1,%2,%3}, [%4];"
        : "=r"(r[0]), "=r"(r[1]), "=r"(r[2]), "=r"(r[3]) : "r"(addr));
}
__device__ __forceinline__ void ldsm4t(uint32_t* r, uint32_t addr) {
    asm volatile("ldmatrix.sync.aligned.m8n8.x4.trans.shared.b16 {%0,%1,%2,%3}, [%4];"
        : "=r"(r[0]), "=r"(r[1]), "=r"(r[2]), "=r"(r[3]) : "r"(addr));
}
__device__ __forceinline__ void ldsm2(uint32_t* r, uint32_t addr) {
    asm volatile("ldmatrix.sync.aligned.m8n8.x2.shared.b16 {%0,%1}, [%2];"
        : "=r"(r[0]), "=r"(r[1]) : "r"(addr));
}
__device__ __forceinline__ void ldsm2t(uint32_t* r, uint32_t addr) {
    asm volatile("ldmatrix.sync.aligned.m8n8.x2.trans.shared.b16 {%0,%1}, [%2];"
        : "=r"(r[0]), "=r"(r[1]) : "r"(addr));
}

// ---------------- weight convert: row-normalize + scale*1024 -> fp16 ----------------
__global__ void __launch_bounds__(256) wconv_h(const float* __restrict__ w,
                                               __half* __restrict__ wt,
                                               int cols, float alpha, float sqin) {
    __shared__ float red[8];
    const int tid = threadIdx.x;
    const int lane = tid & 31, wrp = tid >> 5;
    const int row = blockIdx.x;
    const float* wr = w + (size_t)row * cols;
    const int c4 = cols >> 2;
    float acc = 0.f;
    for (int j = tid; j < c4; j += 256) {
        float4 v = ((const float4*)wr)[j];
        acc += v.x * v.x + v.y * v.y + v.z * v.z + v.w * v.w;
    }
    acc = wredsum(acc);
    if (lane == 0) red[wrp] = acc;
    __syncthreads();
    float tot = red[0] + red[1] + red[2] + red[3] + red[4] + red[5] + red[6] + red[7];
    float s = 1024.f / ((sqrtf(tot) * alpha + 1e-4f) * sqin);
    __half* wo = wt + (size_t)row * cols;
    for (int j = tid; j < c4; j += 256) {
        float4 v = ((const float4*)wr)[j];
        *(__half2*)(wo + 4 * j)     = __floats2half2_rn(v.x * s, v.y * s);
        *(__half2*)(wo + 4 * j + 2) = __floats2half2_rn(v.z * s, v.w * s);
    }
}

__global__ void __launch_bounds__(256) rowscale_kernel(const float* __restrict__ w,
                                                       float* __restrict__ s,
                                                       int cols, float alpha, float sqin) {
    __shared__ float red[8];
    const int tid = threadIdx.x;
    const int lane = tid & 31, wrp = tid >> 5;
    const int row = blockIdx.x;
    const float* wr = w + (size_t)row * cols;
    const int c4 = cols >> 2;
    float acc = 0.f;
    for (int j = tid; j < c4; j += 256) {
        float4 v = ((const float4*)wr)[j];
        acc += v.x * v.x + v.y * v.y + v.z * v.z + v.w * v.w;
    }
    acc = wredsum(acc);
    if (lane == 0) red[wrp] = acc;
    __syncthreads();
    if (tid == 0) {
        float tot = red[0] + red[1] + red[2] + red[3] + red[4] + red[5] + red[6] + red[7];
        s[row] = 1.f / ((sqrtf(tot) * alpha + 1e-4f) * sqin);
    }
}

// ---------------- conditioning (fp32 path) ----------------
__global__ void __launch_bounds__(256) cond_act_kernel(const float* __restrict__ c) {
    int idx = blockIdx.x * 256 + threadIdx.x;
    float v = c[idx];
    float si = v / (1.f + expf(-v)) * INV_SILU;
    g_ccs[idx] = si * g_s_cond[idx & (HID - 1)];
}

__global__ void __launch_bounds__(256) cond_gemm_part(const float* __restrict__ w) {
    __shared__ float cs[4 * 128];
    const int tid = threadIdx.x;
    const int jb = blockIdx.x, ks = blockIdx.y;
    const int k0 = ks * 128;
    for (int t = tid; t < 512; t += 256) {
        int bidx = t >> 7, kk = t & 127;
        cs[t] = g_ccs[bidx * HID + k0 + kk];
    }
    __syncthreads();
    int j = jb * 256 + tid;
    float a0 = 0.f, a1 = 0.f, a2 = 0.f, a3 = 0.f;
    for (int kk = 0; kk < 128; kk++) {
        float wv = w[(size_t)(k0 + kk) * (2 * HID) + j];
        a0 = fmaf(cs[kk], wv, a0);
        a1 = fmaf(cs[128 + kk], wv, a1);
        a2 = fmaf(cs[256 + kk], wv, a2);
        a3 = fmaf(cs[384 + kk], wv, a3);
    }
    g_condp[ks][0 * 2048 + j] = a0;
    g_condp[ks][1 * 2048 + j] = a1;
    g_condp[ks][2 * 2048 + j] = a2;
    g_condp[ks][3 * 2048 + j] = a3;
}

__global__ void __launch_bounds__(256) cond_gemm_reduce() {
    int i = blockIdx.x * 256 + threadIdx.x;
    float s = 0.f;
    #pragma unroll
    for (int ks = 0; ks < 8; ks++) s += g_condp[ks][i];
    g_cond[i] = s;
}

// ---------------- xcond -> fp16 (warp per row, no block barrier) ----------------
__global__ void __launch_bounds__(256) xcond_kernel(const float* __restrict__ x,
                                                    __half* __restrict__ out) {
    const int lane = threadIdx.x & 31, wrp = threadIdx.x >> 5;
    const int row = blockIdx.x * 8 + wrp;
    const int b = row >> 10;
    const float4* xr = (const float4*)(x + (size_t)row * HID);
    float4 v[8];
    float acc = 0.f;
    #pragma unroll
    for (int i = 0; i < 8; i++) {
        v[i] = xr[lane + 32 * i];
        acc += v[i].x * v[i].x + v[i].y * v[i].y + v[i].z * v[i].z + v[i].w * v[i].w;
    }
    acc = wredsum(acc);
    float rms = rsqrtf(acc * (1.f / HID) + 1e-4f);
    const float* gs = g_cond + (size_t)b * 2 * HID;
    __half* orow = out + (size_t)row * HID;
    #pragma unroll
    for (int i = 0; i < 8; i++) {
        int k0 = (lane + 32 * i) * 4;
        float4 gn = *(const float4*)(gs + k0);
        float4 sh = *(const float4*)(gs + HID + k0);
        float o0 = v[i].x * rms * (1.f + gn.x) + sh.x;
        float o1 = v[i].y * rms * (1.f + gn.y) + sh.y;
        float o2 = v[i].z * rms * (1.f + gn.z) + sh.z;
        float o3 = v[i].w * rms * (1.f + gn.w) + sh.w;
        *(__half2*)(orow + k0)     = __floats2half2_rn(o0, o1);
        *(__half2*)(orow + k0 + 2) = __floats2half2_rn(o2, o3);
    }
}

// ---------------- qkv normalize + head split -> fp16 (1 barrier) ----------------
__global__ void __launch_bounds__(256) qkv_norm_kernel() {
    __shared__ float red[24];
    __shared__ float sqr[16], skr[16];
    const int tid = threadIdx.x;
    const int lane = tid & 31, wrp = tid >> 5;
    const int row = blockIdx.x;
    const __half2* qr2 = (const __half2*)(g_qkvh + (size_t)row * 3 * HID);
    float2 a0 = __half22float2(qr2[tid]);
    float2 a1 = __half22float2(qr2[tid + 256]);
    float2 b0 = __half22float2(qr2[512 + tid]);
    float2 b1 = __half22float2(qr2[512 + tid + 256]);
    float2 c0 = __half22float2(qr2[1024 + tid]);
    float2 c1 = __half22float2(qr2[1024 + tid + 256]);
    float qh0 = a0.x * a0.x + a0.y * a0.y;
    float qh1 = a1.x * a1.x + a1.y * a1.y;
    float kh0 = b0.x * b0.x + b0.y * b0.y;
    float kh1 = b1.x * b1.x + b1.y * b1.y;
    float av  = c0.x * c0.x + c0.y * c0.y + c1.x * c1.x + c1.y * c1.y;
    float aq = qh0 + qh1, ak = kh0 + kh1;
    aq = wredsum(aq); ak = wredsum(ak); av = wredsum(av);
    qh0 = wredsum(qh0); qh1 = wredsum(qh1);
    kh0 = wredsum(kh0); kh1 = wredsum(kh1);
    if (lane == 0) {
        red[wrp] = aq; red[8 + wrp] = ak; red[16 + wrp] = av;
        sqr[wrp] = qh0; sqr[8 + wrp] = qh1;
        skr[wrp] = kh0; skr[8 + wrp] = kh1;
    }
    __syncthreads();
    float gq = 0.f, gk = 0.f, gv = 0.f;
    #pragma unroll
    for (int i = 0; i < 8; i++) { gq += red[i]; gk += red[8 + i]; gv += red[16 + i]; }
    float rq = rsqrtf(gq * (1.f / HID) + 1e-4f);
    float rk = rsqrtf(gk * (1.f / HID) + 1e-4f);
    float rv = rsqrtf(gv * (1.f / HID) + 1e-4f);
    const int h0 = wrp, h1 = wrp + 8;
    float scq0 = rq * rsqrtf(rq * rq * sqr[h0] + 1e-6f) * 0.125f;
    float scq1 = rq * rsqrtf(rq * rq * sqr[h1] + 1e-6f) * 0.125f;
    float sck0 = rk * rsqrtf(rk * rk * skr[h0] + 1e-6f);
    float sck1 = rk * rsqrtf(rk * rk * skr[h1] + 1e-6f);
    const int b = row >> 10, n = row & (NN - 1);
    size_t o0 = ((size_t)(b * NHEADS + h0) * NN + n) * DHEAD + 2 * lane;
    size_t o1 = ((size_t)(b * NHEADS + h1) * NN + n) * DHEAD + 2 * lane;
    *(__half2*)(g_qh + o0) = __floats2half2_rn(a0.x * scq0, a0.y * scq0);
    *(__half2*)(g_qh + o1) = __floats2half2_rn(a1.x * scq1, a1.y * scq1);
    *(__half2*)(g_kh + o0) = __floats2half2_rn(b0.x * sck0, b0.y * sck0);
    *(__half2*)(g_kh + o1) = __floats2half2_rn(b1.x * sck1, b1.y * sck1);
    *(__half2*)(g_vh + o0) = __floats2half2_rn(c0.x * rv, c0.y * rv);
    *(__half2*)(g_vh + o1) = __floats2half2_rn(c1.x * rv, c1.y * rv);
}

// ---------------- fp16 flash attention ----------------
#define ATTH_SMEM (2*(64*72 + 64*72)*2)
__global__ void __launch_bounds__(256) attn_h_kernel() {
    extern __shared__ __half smh[];
    __half* Ks = smh;
    __half* Vs = smh + 2 * 64 * 72;
    const int tid = threadIdx.x;
    const int lane = tid & 31, w = tid >> 5;
    const int g = lane >> 2, tg = lane & 3;
    const int bh = blockIdx.y, q0 = blockIdx.x * 128;
    const int b = bh >> 4, h = bh & 15;
    const __half* Qg = g_qh + (size_t)bh * (NN * DHEAD);
    const __half* Kg = g_kh + (size_t)bh * (NN * DHEAD);
    const __half* Vg = g_vh + (size_t)bh * (NN * DHEAD);
    const uint32_t sK = (uint32_t)__cvta_generic_to_shared(Ks);
    const uint32_t sV = (uint32_t)__cvta_generic_to_shared(Vs);

    uint32_t qf[4][4];
    {
        const int r0 = q0 + w * 16;
        #pragma unroll
        for (int kk = 0; kk < 4; kk++) {
            qf[kk][0] = *(const uint32_t*)(Qg + (size_t)(r0 + g) * 64 + kk * 16 + 2 * tg);
            qf[kk][1] = *(const uint32_t*)(Qg + (size_t)(r0 + g + 8) * 64 + kk * 16 + 2 * tg);
            qf[kk][2] = *(const uint32_t*)(Qg + (size_t)(r0 + g) * 64 + kk * 16 + 2 * tg + 8);
            qf[kk][3] = *(const uint32_t*)(Qg + (size_t)(r0 + g + 8) * 64 + kk * 16 + 2 * tg + 8);
        }
    }

    float Of[8][4];
    #pragma unroll
    for (int nt = 0; nt < 8; nt++)
        #pragma unroll
        for (int r = 0; r < 4; r++) Of[nt][r] = 0.f;
    float rs0 = 0.f, rs1 = 0.f;

    for (int id = tid; id < 512; id += 256) {
        int r = id >> 3, ch = (id & 7) * 8;
        cp16(sK + (r * 72 + ch) * 2, Kg + r * 64 + ch);
        cp16(sV + (r * 72 + ch) * 2, Vg + r * 64 + ch);
    }
    CP_COMMIT();

    for (int kt = 0; kt < 16; kt++) {
        CP_WAIT0();
        __syncthreads();
        const int buf = kt & 1;
        if (kt + 1 < 16) {
            const int nb = buf ^ 1;
            const __half* Kn = Kg + (size_t)(kt + 1) * 4096;
            const __half* Vn = Vg + (size_t)(kt + 1) * 4096;
            for (int id = tid; id < 512; id += 256) {
                int r = id >> 3, ch = (id & 7) * 8;
                cp16(sK + (nb * 64 * 72 + r * 72 + ch) * 2, Kn + r * 64 + ch);
                cp16(sV + (nb * 64 * 72 + r * 72 + ch) * 2, Vn + r * 64 + ch);
            }
            CP_COMMIT();
        }
        float sc[8][4];
        #pragma unroll
        for (int nt = 0; nt < 8; nt++) {
            sc[nt][0] = sc[nt][1] = sc[nt][2] = sc[nt][3] = 0.f;
            #pragma unroll
            for (int kk = 0; kk < 4; kk++) {
                uint32_t bb[2];
                ldsm2(bb, sK + (buf * 64 * 72 + (nt * 8 + (lane & 7)) * 72
                                 + kk * 16 + (((lane & 15) >> 3) << 3)) * 2);
                mma_f16(sc[nt], qf[kk], bb);
            }
        }
        #pragma unroll
        for (int nt = 0; nt < 8; nt++) {
            sc[nt][0] = __expf(sc[nt][0]); sc[nt][1] = __expf(sc[nt][1]);
            sc[nt][2] = __expf(sc[nt][2]); sc[nt][3] = __expf(sc[nt][3]);
            rs0 += sc[nt][0] + sc[nt][1];
            rs1 += sc[nt][2] + sc[nt][3];
        }
        #pragma unroll
        for (int kc = 0; kc < 4; kc++) {
            uint32_t pa[4];
            pa[0] = h2_as_u32(__floats2half2_rn(sc[2*kc][0],   sc[2*kc][1]));
            pa[1] = h2_as_u32(__floats2half2_rn(sc[2*kc][2],   sc[2*kc][3]));
            pa[2] = h2_as_u32(__floats2half2_rn(sc[2*kc+1][0], sc[2*kc+1][1]));
            pa[3] = h2_as_u32(__floats2half2_rn(sc[2*kc+1][2], sc[2*kc+1][3]));
            #pragma unroll
            for (int nt = 0; nt < 8; nt++) {
                uint32_t bb[2];
                ldsm2t(bb, sV + (buf * 64 * 72 + (kc * 16 + (lane & 15)) * 72 + nt * 8) * 2);
                mma_f16(Of[nt], pa, bb);
            }
        }
    }

    rs0 += __shfl_xor_sync(0xffffffffu, rs0, 1);
    rs0 += __shfl_xor_sync(0xffffffffu, rs0, 2);
    rs1 += __shfl_xor_sync(0xffffffffu, rs1, 1);
    rs1 += __shfl_xor_sync(0xffffffffu, rs1, 2);
    float inv0 = 1.f / rs0, inv1 = 1.f / rs1;

    const int n0 = q0 + w * 16 + g;
    #pragma unroll
    for (int nt = 0; nt < 8; nt++) {
        int col = h * 64 + nt * 8 + 2 * tg;
        __half2* p0 = (__half2*)(g_xattnh + ((size_t)b * NN + n0) * HID + col);
        __half2* p1 = (__half2*)(g_xattnh + ((size_t)b * NN + n0 + 8) * HID + col);
        *p0 = __floats2half2_rn(Of[nt][0] * inv0, Of[nt][1] * inv0);
        *p1 = __floats2half2_rn(Of[nt][2] * inv1, Of[nt][3] * inv1);
    }
}

// ---------------- fp16 GEMM, 3-stage pipeline, ldsm4t B-frags ----------------
#define TGH_SMEM (3*(128*40 + 32*136) * 2)   // 56832 B
__device__ __forceinline__ void tg_load(const __half* A, const __half* B,
                                        uint32_t sA, uint32_t sB,
                                        int st, int kt, int tid,
                                        int crow, int ccol, int K, int N) {
    const __half* Ags = A + (size_t)kt * 32;
    const __half* Bgs = B + (size_t)kt * 32 * N;
    #pragma unroll
    for (int s = 0; s < 2; s++) {
        int id = tid + s * 256;
        int r = id >> 2, ch = (id & 3) * 8;
        cp16(sA + ((st * 128 + r) * 40 + ch) * 2, Ags + (size_t)(crow + r) * K + ch);
        int rb = id >> 4, cb = (id & 15) * 8;
        cp16(sB + ((st * 32 + rb) * 136 + cb) * 2, Bgs + (size_t)rb * N + ccol + cb);
    }
    CP_COMMIT();
}

__global__ void __launch_bounds__(256) tgemm_h(const __half* __restrict__ A,
                                               const __half* __restrict__ B,
                                               __half* __restrict__ C,
                                               int M, int N, int K) {
    extern __shared__ __half smh[];
    __half* As = smh;                  // [3][128][40]
    __half* Bs = smh + 3 * 128 * 40;   // [3][32][136]
    const int tid = threadIdx.x;
    const int crow = blockIdx.y * 128;
    const int ccol = blockIdx.x * 128;
    const int lane = tid & 31, wid = tid >> 5;
    const int wm = wid & 1, wn = wid >> 1;
    const int g = lane >> 2, tg = lane & 3;
    const uint32_t sA = (uint32_t)__cvta_generic_to_shared(As);
    const uint32_t sB = (uint32_t)__cvta_generic_to_shared(Bs);

    float acc[4][4][4];
    #pragma unroll
    for (int i = 0; i < 4; i++)
        #pragma unroll
        for (int j = 0; j < 4; j++)
            #pragma unroll
            for (int r = 0; r < 4; r++) acc[i][j][r] = 0.f;

    tg_load(A, B, sA, sB, 0, 0, tid, crow, ccol, K, N);
    tg_load(A, B, sA, sB, 1, 1, tid, crow, ccol, K, N);

    const int nk = K >> 5;
    int st = 0;
    for (int it = 0; it < nk; it++) {
        if (it + 1 < nk) { CP_WAIT1(); } else { CP_WAIT0(); }
        __syncthreads();
        if (it + 2 < nk) {
            int ns = st + 2; if (ns >= 3) ns -= 3;
            tg_load(A, B, sA, sB, ns, it + 2, tid, crow, ccol, K, N);
        }
        #pragma unroll
        for (int ks = 0; ks < 32; ks += 16) {
            uint32_t af[4][4];
            #pragma unroll
            for (int mt = 0; mt < 4; mt++) {
                int r = wm * 64 + mt * 16 + (lane & 15);
                int c = ks + ((lane >> 4) << 3);
                ldsm4(af[mt], sA + ((st * 128 + r) * 40 + c) * 2);
            }
            uint32_t bf[2][4];
            #pragma unroll
            for (int ntp = 0; ntp < 2; ntp++) {
                int r = ks + (lane & 15);
                int c = wn * 32 + ntp * 16 + ((lane >> 4) << 3);
                ldsm4t(bf[ntp], sB + ((st * 32 + r) * 136 + c) * 2);
            }
            #pragma unroll
            for (int mt = 0; mt < 4; mt++) {
                mma_f16(acc[mt][0], af[mt], &bf[0][0]);
                mma_f16(acc[mt][1], af[mt], &bf[0][2]);
                mma_f16(acc[mt][2], af[mt], &bf[1][0]);
                mma_f16(acc[mt][3], af[mt], &bf[1][2]);
            }
        }
        __syncthreads();
        if (++st == 3) st = 0;
    }

    #pragma unroll
    for (int mt = 0; mt < 4; mt++) {
        const int r0 = crow + wm * 64 + mt * 16 + g;
        #pragma unroll
        for (int nt = 0; nt < 4; nt++) {
            const int c0 = ccol + wn * 32 + nt * 8 + 2 * tg;
            *(__half2*)(C + (size_t)r0 * N + c0) =
                __floats2half2_rn(acc[mt][nt][0] * OUTSCALE, acc[mt][nt][1] * OUTSCALE);
            *(__half2*)(C + (size_t)(r0 + 8) * N + c0) =
                __floats2half2_rn(acc[mt][nt][2] * OUTSCALE, acc[mt][nt][3] * OUTSCALE);
        }
    }
}

// ---------------- post-attention (warp per row) ----------------
__global__ void __launch_bounds__(256) post_attn_kernel(const float* __restrict__ x,
                                                        const float* __restrict__ agp) {
    const int lane = threadIdx.x & 31, wrp = threadIdx.x >> 5;
    const int row = blockIdx.x * 8 + wrp;
    const int b = row >> 10;
    const uint4* ar4 = (const uint4*)(g_aoh + (size_t)row * HID);   // 128 uint4 (8 halves)
    float a[32];
    float acc = 0.f;
    #pragma unroll
    for (int i = 0; i < 4; i++) {
        uint4 u = ar4[lane + 32 * i];
        float2 f0 = __half22float2(*(__half2*)&u.x);
        float2 f1 = __half22float2(*(__half2*)&u.y);
        float2 f2 = __half22float2(*(__half2*)&u.z);
        float2 f3 = __half22float2(*(__half2*)&u.w);
        a[8*i+0] = f0.x; a[8*i+1] = f0.y; a[8*i+2] = f1.x; a[8*i+3] = f1.y;
        a[8*i+4] = f2.x; a[8*i+5] = f2.y; a[8*i+6] = f3.x; a[8*i+7] = f3.y;
        acc += f0.x*f0.x + f0.y*f0.y + f1.x*f1.x + f1.y*f1.y
             + f2.x*f2.x + f2.y*f2.y + f3.x*f3.x + f3.y*f3.y;
    }
    acc = wredsum(acc);
    float rms = rsqrtf(acc * (1.f / HID) + 1e-4f);
    float eg = expf(agp[0]) * rms;
    const float4* xr4 = (const float4*)(x + (size_t)row * HID);
    float4* xm4 = (float4*)(g_xmid + (size_t)row * HID);
    float acc2 = 0.f;
    #pragma unroll
    for (int i = 0; i < 4; i++) {
        int i4 = 2 * (lane + 32 * i);
        float4 x0 = xr4[i4], x1 = xr4[i4 + 1];
        float m0 = (0.7f * x0.x + 0.3f * a[8*i+0] * eg) * MP_ADD_INV;
        float m1 = (0.7f * x0.y + 0.3f * a[8*i+1] * eg) * MP_ADD_INV;
        float m2 = (0.7f * x0.z + 0.3f * a[8*i+2] * eg) * MP_ADD_INV;
        float m3 = (0.7f * x0.w + 0.3f * a[8*i+3] * eg) * MP_ADD_INV;
        float m4 = (0.7f * x1.x + 0.3f * a[8*i+4] * eg) * MP_ADD_INV;
        float m5 = (0.7f * x1.y + 0.3f * a[8*i+5] * eg) * MP_ADD_INV;
        float m6 = (0.7f * x1.z + 0.3f * a[8*i+6] * eg) * MP_ADD_INV;
        float m7 = (0.7f * x1.w + 0.3f * a[8*i+7] * eg) * MP_ADD_INV;
        xm4[i4]     = make_float4(m0, m1, m2, m3);
        xm4[i4 + 1] = make_float4(m4, m5, m6, m7);
        a[8*i+0]=m0; a[8*i+1]=m1; a[8*i+2]=m2; a[8*i+3]=m3;
        a[8*i+4]=m4; a[8*i+5]=m5; a[8*i+6]=m6; a[8*i+7]=m7;
        acc2 += m0*m0 + m1*m1 + m2*m2 + m3*m3 + m4*m4 + m5*m5 + m6*m6 + m7*m7;
    }
    acc2 = wredsum(acc2);
    float rms2 = rsqrtf(acc2 * (1.f / HID) + 1e-4f);
    const float* gs = g_cond + (size_t)b * 2 * HID;
    uint4* orow = (uint4*)(g_xc2h + (size_t)row * HID);
    #pragma unroll
    for (int i = 0; i < 4; i++) {
        int k0 = (lane + 32 * i) * 8;
        float4 gn0 = *(const float4*)(gs + k0);
        float4 gn1 = *(const float4*)(gs + k0 + 4);
        float4 sh0 = *(const float4*)(gs + HID + k0);
        float4 sh1 = *(const float4*)(gs + HID + k0 + 4);
        uint4 o;
        o.x = h2_as_u32(__floats2half2_rn(a[8*i+0]*rms2*(1.f+gn0.x)+sh0.x,
                                          a[8*i+1]*rms2*(1.f+gn0.y)+sh0.y));
        o.y = h2_as_u32(__floats2half2_rn(a[8*i+2]*rms2*(1.f+gn0.z)+sh0.z,
                                          a[8*i+3]*rms2*(1.f+gn0.w)+sh0.w));
        o.z = h2_as_u32(__floats2half2_rn(a[8*i+4]*rms2*(1.f+gn1.x)+sh1.x,
                                          a[8*i+5]*rms2*(1.f+gn1.y)+sh1.y));
        o.w = h2_as_u32(__floats2half2_rn(a[8*i+6]*rms2*(1.f+gn1.z)+sh1.z,
                                          a[8*i+7]*rms2*(1.f+gn1.w)+sh1.w));
        orow[lane + 32 * i] = o;
    }
}

// ---------------- MLP hidden activation (block per row, 1 barrier) ----------------
__global__ void __launch_bounds__(256) mlp_act_kernel() {
    __shared__ float red[8];
    const int tid = threadIdx.x;
    const int lane = tid & 31, wrp = tid >> 5;
    const int row = blockIdx.x;
    const __half2* hr2 = (const __half2*)(g_hh + (size_t)row * MLPD);
    float2 v[8];
    float acc = 0.f;
    #pragma unroll
    for (int i = 0; i < 8; i++) {
        v[i] = __half22float2(hr2[tid + 256 * i]);
        acc += v[i].x * v[i].x + v[i].y * v[i].y;
    }
    acc = wredsum(acc);
    if (lane == 0) red[wrp] = acc;
    __syncthreads();
    float tot = red[0] + red[1] + red[2] + red[3] + red[4] + red[5] + red[6] + red[7];
    float rms = rsqrtf(tot * (1.f / MLPD) + 1e-4f);
    __half2* o2 = (__half2*)(g_h2h + (size_t)row * MLPD);
    #pragma unroll
    for (int i = 0; i < 8; i++) {
        float u0 = v[i].x * rms, u1 = v[i].y * rms;
        float s0 = u0 / (1.f + __expf(-u0)) * INV_SILU;
        float s1 = u1 / (1.f + __expf(-u1)) * INV_SILU;
        o2[tid + 256 * i] = __floats2half2_rn(s0, s1);
    }
}

// ---------------- final (warp per row) ----------------
__global__ void __launch_bounds__(256) final_kernel(const float* __restrict__ mgp,
                                                    float* __restrict__ out) {
    const int lane = threadIdx.x & 31, wrp = threadIdx.x >> 5;
    const int row = blockIdx.x * 8 + wrp;
    const uint4* mr4 = (const uint4*)(g_mh + (size_t)row * HID);
    float a[32];
    float acc = 0.f;
    #pragma unroll
    for (int i = 0; i < 4; i++) {
        uint4 u = mr4[lane + 32 * i];
        float2 f0 = __half22float2(*(__half2*)&u.x);
        float2 f1 = __half22float2(*(__half2*)&u.y);
        float2 f2 = __half22float2(*(__half2*)&u.z);
        float2 f3 = __half22float2(*(__half2*)&u.w);
        a[8*i+0] = f0.x; a[8*i+1] = f0.y; a[8*i+2] = f1.x; a[8*i+3] = f1.y;
        a[8*i+4] = f2.x; a[8*i+5] = f2.y; a[8*i+6] = f3.x; a[8*i+7] = f3.y;
        acc += f0.x*f0.x + f0.y*f0.y + f1.x*f1.x + f1.y*f1.y
             + f2.x*f2.x + f2.y*f2.y + f3.x*f3.x + f3.y*f3.y;
    }
    acc = wredsum(acc);
    float rms = rsqrtf(acc * (1.f / HID) + 1e-4f);
    float eg = expf(mgp[0]) * rms;
    const float4* xm4 = (const float4*)(g_xmid + (size_t)row * HID);
    float4* or4 = (float4*)(out + (size_t)row * HID);
    #pragma unroll
    for (int i = 0; i < 4; i++) {
        int i4 = 2 * (lane + 32 * i);
        float4 x0 = xm4[i4], x1 = xm4[i4 + 1];
        float4 o0, o1;
        o0.x = (0.7f * x0.x + 0.3f * a[8*i+0] * eg) * MP_ADD_INV;
        o0.y = (0.7f * x0.y + 0.3f * a[8*i+1] * eg) * MP_ADD_INV;
        o0.z = (0.7f * x0.z + 0.3f * a[8*i+2] * eg) * MP_ADD_INV;
        o0.w = (0.7f * x0.w + 0.3f * a[8*i+3] * eg) * MP_ADD_INV;
        o1.x = (0.7f * x1.x + 0.3f * a[8*i+4] * eg) * MP_ADD_INV;
        o1.y = (0.7f * x1.y + 0.3f * a[8*i+5] * eg) * MP_ADD_INV;
        o1.z = (0.7f * x1.z + 0.3f * a[8*i+6] * eg) * MP_ADD_INV;
        o1.w = (0.7f * x1.w + 0.3f * a[8*i+7] * eg) * MP_ADD_INV;
        or4[i4]     = o0;
        or4[i4 + 1] = o1;
    }
}

// ---------------- launch ----------------
extern "C" void kernel_launch(void* const* d_in, const int* in_sizes, int n_in,
                              void* d_out, int out_size) {
    (void)in_sizes; (void)n_in; (void)out_size;
    const float* x         = (const float*)d_in[0];
    const float* c         = (const float*)d_in[1];
    const float* w_cond    = (const float*)d_in[2];
    const float* w_qkv     = (const float*)d_in[3];
    const float* w_out     = (const float*)d_in[4];
    const float* w_mlp1    = (const float*)d_in[5];
    const float* w_mlp2    = (const float*)d_in[6];
    const float* attn_gain = (const float*)d_in[7];
    const float* mlp_gain  = (const float*)d_in[8];
    float* out = (float*)d_out;

    void *p_scond, *p_xc1, *p_qkv, *p_xattn, *p_ao, *p_xc2, *p_h, *p_h2, *p_m;
    void *p_wq, *p_wo, *p_wm1, *p_wm2;
    cudaGetSymbolAddress(&p_scond, g_s_cond);
    cudaGetSymbolAddress(&p_xc1,   g_xc1h);
    cudaGetSymbolAddress(&p_qkv,   g_qkvh);
    cudaGetSymbolAddress(&p_xattn, g_xattnh);
    cudaGetSymbolAddress(&p_ao,    g_aoh);
    cudaGetSymbolAddress(&p_xc2,   g_xc2h);
    cudaGetSymbolAddress(&p_h,     g_hh);
    cudaGetSymbolAddress(&p_h2,    g_h2h);
    cudaGetSymbolAddress(&p_m,     g_mh);
    cudaGetSymbolAddress(&p_wq,    g_wqh);
    cudaGetSymbolAddress(&p_wo,    g_woh);
    cudaGetSymbolAddress(&p_wm1,   g_wm1h);
    cudaGetSymbolAddress(&p_wm2,   g_wm2h);

    cudaFuncSetAttribute(attn_h_kernel, cudaFuncAttributeMaxDynamicSharedMemorySize, ATTH_SMEM);
    cudaFuncSetAttribute(tgemm_h, cudaFuncAttributeMaxDynamicSharedMemorySize, TGH_SMEM);

    // weight preprocessing (fp16, x1024)
    wconv_h<<<1024, 256>>>(w_qkv,  (__half*)p_wq,  3072, 55.42562584220407f, 32.f);
    wconv_h<<<1024, 256>>>(w_out,  (__half*)p_wo,  1024, 32.f, 32.f);
    wconv_h<<<1024, 256>>>(w_mlp1, (__half*)p_wm1, 4096, 64.f, 32.f);
    wconv_h<<<4096, 256>>>(w_mlp2, (__half*)p_wm2, 1024, 32.f, 64.f);
    rowscale_kernel<<<1024, 256>>>(w_cond, (float*)p_scond, 2048, 45.25483399593904f, 32.f);

    // conditioning
    cond_act_kernel<<<16, 256>>>(c);
    cond_gemm_part<<<dim3(8, 8), 256>>>(w_cond);
    cond_gemm_reduce<<<32, 256>>>();

    // attention branch
    xcond_kernel<<<512, 256>>>(x, (__half*)p_xc1);
    tgemm_h<<<dim3(24, 32), 256, TGH_SMEM>>>((const __half*)p_xc1, (const __half*)p_wq,
                                             (__half*)p_qkv, ROWS, 3 * HID, HID);
    qkv_norm_kernel<<<ROWS, 256>>>();
    attn_h_kernel<<<dim3(8, 64), 256, ATTH_SMEM>>>();
    tgemm_h<<<dim3(8, 32), 256, TGH_SMEM>>>((const __half*)p_xattn, (const __half*)p_wo,
                                            (__half*)p_ao, ROWS, HID, HID);
    post_attn_kernel<<<512, 256>>>(x, attn_gain);

    // MLP branch
    tgemm_h<<<dim3(32, 32), 256, TGH_SMEM>>>((const __half*)p_xc2, (const __half*)p_wm1,
                                             (__half*)p_h, ROWS, MLPD, HID);
    mlp_act_kernel<<<ROWS, 256>>>();
    tgemm_h<<<dim3(8, 32), 256, TGH_SMEM>>>((const __half*)p_h2, (const __half*)p_wm2,
                                            (__half*)p_m, ROWS, HID, MLPD);
    final_kernel<<<512, 256>>>(mlp_gain, out);
}